// round 1
// baseline (speedup 1.0000x reference)
#include <cuda_runtime.h>
#include <math.h>

#define NB 4
#define BATCH 2
#define HH 64
#define HW 4096
#define F 64
#define DK 8
#define CAT 256
#define CF 320

// ---------------- scratch (device globals; no allocation allowed) ----------
__device__ float g_fused[BATCH * HW * CF];          // [b][pos][320]
__device__ float g_q[BATCH * NB * HW * DK];         // [bb][pos][8]  bb = b*NB+br
__device__ float g_k[BATCH * NB * HW * DK];
__device__ float g_v[BATCH * NB * HW * F];          // [bb][pos][64]
__device__ float g_pool[NB * BATCH * HW * 16];      // [j*2+b][pos][16] (over-alloc)

// ---------------- K1: dilated 3x3 conv + BN + ReLU -> fused[.., br*64..] ---
__global__ void k_conv(const float* __restrict__ x, const float* __restrict__ w,
                       const float* __restrict__ cb, const float* __restrict__ bg,
                       const float* __restrict__ bbe, const float* __restrict__ bm,
                       const float* __restrict__ bv) {
    int co = threadIdx.x;
    int x0 = blockIdx.x * 4, y = blockIdx.y;
    int b = blockIdx.z >> 2, br = blockIdx.z & 3;
    int d = 1 << br;  // dilations 1,2,4,8
    float a0 = 0.f, a1 = 0.f, a2 = 0.f, a3 = 0.f;
    const float* wb = w + br * 9 * 64 * 64 + co;
#pragma unroll
    for (int ky = 0; ky < 3; ++ky) {
        int iy = y + d * (ky - 1);
        if ((unsigned)iy >= 64u) continue;
        const float* xr = x + ((b * 64 + iy) * 64) * 64;
#pragma unroll
        for (int kx = 0; kx < 3; ++kx) {
            int ix = x0 + d * (kx - 1);
            const float* wp = wb + (ky * 3 + kx) * 64 * 64;
            bool v0 = (unsigned)ix < 64u;
            bool v1 = (unsigned)(ix + 1) < 64u;
            bool v2 = (unsigned)(ix + 2) < 64u;
            bool v3 = (unsigned)(ix + 3) < 64u;
            const float* xp = xr + ix * 64;
            float4 z4 = make_float4(0.f, 0.f, 0.f, 0.f);
#pragma unroll 4
            for (int ci = 0; ci < 64; ci += 4) {
                float4 q0 = v0 ? *(const float4*)(xp + ci) : z4;
                float4 q1 = v1 ? *(const float4*)(xp + 64 + ci) : z4;
                float4 q2 = v2 ? *(const float4*)(xp + 128 + ci) : z4;
                float4 q3 = v3 ? *(const float4*)(xp + 192 + ci) : z4;
                float w0 = wp[(ci + 0) * 64], w1 = wp[(ci + 1) * 64];
                float w2 = wp[(ci + 2) * 64], w3 = wp[(ci + 3) * 64];
                a0 += q0.x * w0 + q0.y * w1 + q0.z * w2 + q0.w * w3;
                a1 += q1.x * w0 + q1.y * w1 + q1.z * w2 + q1.w * w3;
                a2 += q2.x * w0 + q2.y * w1 + q2.z * w2 + q2.w * w3;
                a3 += q3.x * w0 + q3.y * w1 + q3.z * w2 + q3.w * w3;
            }
        }
    }
    int idx = br * 64 + co;
    float bias = cb[idx];
    float sc = bg[idx] * rsqrtf(bv[idx] + 1e-3f);
    float sh = bbe[idx] - bm[idx] * sc;
    float* f = g_fused + ((size_t)(b * HW) + y * 64 + x0) * CF + br * 64 + co;
    f[0]       = fmaxf((a0 + bias) * sc + sh, 0.f);
    f[CF]      = fmaxf((a1 + bias) * sc + sh, 0.f);
    f[2 * CF]  = fmaxf((a2 + bias) * sc + sh, 0.f);
    f[3 * CF]  = fmaxf((a3 + bias) * sc + sh, 0.f);
}

// ---------------- K2: 1x1 convs -> q,k,v ----------------------------------
__global__ void k_qkv(const float* __restrict__ qw, const float* __restrict__ qb,
                      const float* __restrict__ kw, const float* __restrict__ kb,
                      const float* __restrict__ vw, const float* __restrict__ vb) {
    __shared__ float bs[64];
    int n = blockIdx.x, br = blockIdx.y, b = blockIdx.z;
    int t = threadIdx.x;
    bs[t] = g_fused[((size_t)(b * HW + n)) * CF + br * 64 + t];
    __syncthreads();
    int bb = b * NB + br;
    {
        const float* wv = vw + br * 4096 + t;
        float a = vb[br * 64 + t];
#pragma unroll 8
        for (int ci = 0; ci < 64; ++ci) a += bs[ci] * wv[ci * 64];
        g_v[((size_t)bb * HW + n) * 64 + t] = a;
    }
    if (t < 16) {
        int dd = t & 7;
        const float* wq = (t < 8 ? qw : kw) + br * 512 + dd;
        float a = (t < 8 ? qb : kb)[br * 8 + dd];
#pragma unroll 8
        for (int ci = 0; ci < 64; ++ci) a += bs[ci] * wq[ci * 8];
        (t < 8 ? g_q : g_k)[((size_t)bb * HW + n) * 8 + dd] = a;
    }
}

// ---------------- K3: fused softmax-attention, fused += gamma * (P V) -----
__global__ void __launch_bounds__(256) k_attn(const float* __restrict__ gamma) {
    extern __shared__ float Vs[];  // 256 * 64 floats = 64 KB
    int br = blockIdx.y, b = blockIdx.z;
    int bb = b * NB + br;
    const float4* kp = (const float4*)(g_k + (size_t)bb * HW * 8);
    const float* qp = g_q + (size_t)bb * HW * 8;
    const float4* vp = (const float4*)(g_v + (size_t)bb * HW * 64);
    int warp = threadIdx.x >> 5, lane = threadIdx.x & 31;
    int n0 = (blockIdx.x * 8 + warp) * 4;
    float q[4][8];
#pragma unroll
    for (int qi = 0; qi < 4; ++qi) {
        float4 a = *(const float4*)(qp + (n0 + qi) * 8);
        float4 c = *(const float4*)(qp + (n0 + qi) * 8 + 4);
        q[qi][0] = a.x; q[qi][1] = a.y; q[qi][2] = a.z; q[qi][3] = a.w;
        q[qi][4] = c.x; q[qi][5] = c.y; q[qi][6] = c.z; q[qi][7] = c.w;
    }
    // pass 1: row max
    float mx[4] = {-1e30f, -1e30f, -1e30f, -1e30f};
    for (int m = lane; m < HW; m += 32) {
        float4 k0 = kp[m * 2], k1 = kp[m * 2 + 1];
#pragma unroll
        for (int qi = 0; qi < 4; ++qi) {
            float s = q[qi][0] * k0.x + q[qi][1] * k0.y + q[qi][2] * k0.z + q[qi][3] * k0.w
                    + q[qi][4] * k1.x + q[qi][5] * k1.y + q[qi][6] * k1.z + q[qi][7] * k1.w;
            mx[qi] = fmaxf(mx[qi], s);
        }
    }
#pragma unroll
    for (int o = 16; o; o >>= 1)
#pragma unroll
        for (int qi = 0; qi < 4; ++qi)
            mx[qi] = fmaxf(mx[qi], __shfl_xor_sync(0xffffffffu, mx[qi], o));

    // pass 2: exp + Z + PV over smem-staged V tiles
    float Z[4] = {0.f, 0.f, 0.f, 0.f};
    float acc0[4] = {0.f, 0.f, 0.f, 0.f};
    float acc1[4] = {0.f, 0.f, 0.f, 0.f};
    for (int t0 = 0; t0 < HW; t0 += 256) {
        __syncthreads();
        const float4* src = vp + t0 * 16;
        float4* dst = (float4*)Vs;
#pragma unroll
        for (int i = 0; i < 16; ++i) dst[threadIdx.x + i * 256] = src[threadIdx.x + i * 256];
        __syncthreads();
        for (int c = 0; c < 8; ++c) {
            int m = t0 + c * 32 + lane;
            float4 k0 = kp[m * 2], k1 = kp[m * 2 + 1];
            float p[4];
#pragma unroll
            for (int qi = 0; qi < 4; ++qi) {
                float s = q[qi][0] * k0.x + q[qi][1] * k0.y + q[qi][2] * k0.z + q[qi][3] * k0.w
                        + q[qi][4] * k1.x + q[qi][5] * k1.y + q[qi][6] * k1.z + q[qi][7] * k1.w;
                p[qi] = __expf(s - mx[qi]);
                Z[qi] += p[qi];
            }
            const float* vrow = Vs + c * 32 * 64;
#pragma unroll
            for (int j = 0; j < 32; ++j) {
                float v0 = vrow[j * 64 + lane];
                float v1 = vrow[j * 64 + lane + 32];
#pragma unroll
                for (int qi = 0; qi < 4; ++qi) {
                    float pj = __shfl_sync(0xffffffffu, p[qi], j);
                    acc0[qi] += pj * v0;
                    acc1[qi] += pj * v1;
                }
            }
        }
    }
#pragma unroll
    for (int o = 16; o; o >>= 1)
#pragma unroll
        for (int qi = 0; qi < 4; ++qi) Z[qi] += __shfl_xor_sync(0xffffffffu, Z[qi], o);
    float g = gamma[br];
#pragma unroll
    for (int qi = 0; qi < 4; ++qi) {
        float inv = g / Z[qi];
        float* f = g_fused + ((size_t)(b * HW + n0 + qi)) * CF + br * 64;
        f[lane]      += acc0[qi] * inv;
        f[lane + 32] += acc1[qi] * inv;
    }
}

// ---------------- K4: avg-pool(SAME, count excl. pad) + 1x1 conv + BN -----
__global__ void k_pool(const float* __restrict__ pw, const float* __restrict__ pb,
                       const float* __restrict__ pg, const float* __restrict__ pbe,
                       const float* __restrict__ pm, const float* __restrict__ pv) {
    const int PS[4] = {1, 2, 3, 6};
    const int HP[4] = {64, 32, 22, 11};
    const int PLO[4] = {0, 0, 1, 1};
    int j = blockIdx.z >> 1, b = blockIdx.z & 1;
    int hp = HP[j], ps = PS[j], plo = PLO[j];
    int oy = blockIdx.y, ox = blockIdx.x;
    if (oy >= hp || ox >= hp) return;
    __shared__ float avg[256];
    int t = threadIdx.x;
    int ys = oy * ps - plo, xs = ox * ps - plo;
    int ye = min(ys + ps, 64), xe = min(xs + ps, 64);
    ys = max(ys, 0); xs = max(xs, 0);
    float s = 0.f;
    for (int yy = ys; yy < ye; ++yy)
        for (int xx = xs; xx < xe; ++xx)
            s += g_fused[((size_t)(b * HW) + yy * 64 + xx) * CF + t];
    avg[t] = s / (float)((ye - ys) * (xe - xs));
    __syncthreads();
    if (t < 16) {
        float a = pb[j * 16 + t];
        const float* wp = pw + j * 256 * 16 + t;
#pragma unroll 8
        for (int ci = 0; ci < 256; ++ci) a += avg[ci] * wp[ci * 16];
        int idx = j * 16 + t;
        float sc = pg[idx] * rsqrtf(pv[idx] + 1e-3f);
        float sh = pbe[idx] - pm[idx] * sc;
        g_pool[((size_t)((j * 2 + b) * HW) + oy * hp + ox) * 16 + t] = a * sc + sh;
    }
}

// ---------------- K5: bilinear upsample (half-pixel, edge clamp) ----------
__global__ void k_upsample() {
    const int HP[4] = {64, 32, 22, 11};
    int ox = blockIdx.x, oy = blockIdx.y, b = blockIdx.z;
    int t = threadIdx.x;
    int j = t >> 4, c = t & 15;
    int hp = HP[j];
    float scale = hp * (1.f / 64.f);
    float fy = (oy + 0.5f) * scale - 0.5f;
    float fx = (ox + 0.5f) * scale - 0.5f;
    float y0f = floorf(fy), x0f = floorf(fx);
    float ty = fy - y0f, tx = fx - x0f;
    int y0 = min(max((int)y0f, 0), hp - 1);
    int y1 = min(max((int)y0f + 1, 0), hp - 1);
    int xA = min(max((int)x0f, 0), hp - 1);
    int xB = min(max((int)x0f + 1, 0), hp - 1);
    const float* P = g_pool + (size_t)((j * 2 + b) * HW) * 16 + c;
    float v00 = P[(y0 * hp + xA) * 16], v01 = P[(y0 * hp + xB) * 16];
    float v10 = P[(y1 * hp + xA) * 16], v11 = P[(y1 * hp + xB) * 16];
    float val = (1.f - ty) * ((1.f - tx) * v00 + tx * v01)
              + ty * ((1.f - tx) * v10 + tx * v11);
    g_fused[((size_t)(b * HW) + oy * 64 + ox) * CF + 256 + t] = val;
}

// ---------------- K6: 1x1 proj (320->64) + BN + ReLU -> out ---------------
__global__ void k_proj(const float* __restrict__ w, const float* __restrict__ pb,
                       const float* __restrict__ g, const float* __restrict__ be,
                       const float* __restrict__ m, const float* __restrict__ v,
                       float* __restrict__ out) {
    __shared__ float fv[CF];
    int tok = blockIdx.x;
    int t = threadIdx.x;
    for (int i = t; i < CF; i += 64) fv[i] = g_fused[(size_t)tok * CF + i];
    __syncthreads();
    float a = pb[t];
    const float* wp = w + t;
#pragma unroll 8
    for (int ci = 0; ci < CF; ++ci) a += fv[ci] * wp[ci * 64];
    float sc = g[t] * rsqrtf(v[t] + 1e-3f);
    float sh = be[t] - m[t] * sc;
    out[(size_t)tok * 64 + t] = fmaxf(a * sc + sh, 0.f);
}

// ---------------- launch ---------------------------------------------------
extern "C" void kernel_launch(void* const* d_in, const int* in_sizes, int n_in,
                              void* d_out, int out_size) {
    const float* x       = (const float*)d_in[0];
    const float* conv_w  = (const float*)d_in[1];
    const float* conv_b  = (const float*)d_in[2];
    const float* bn_g    = (const float*)d_in[3];
    const float* bn_b    = (const float*)d_in[4];
    const float* bn_m    = (const float*)d_in[5];
    const float* bn_v    = (const float*)d_in[6];
    const float* q_w     = (const float*)d_in[7];
    const float* q_b     = (const float*)d_in[8];
    const float* k_w     = (const float*)d_in[9];
    const float* k_b     = (const float*)d_in[10];
    const float* v_w     = (const float*)d_in[11];
    const float* v_b     = (const float*)d_in[12];
    const float* attn_g  = (const float*)d_in[13];
    const float* ppl_w   = (const float*)d_in[14];
    const float* ppl_b   = (const float*)d_in[15];
    const float* ppl_bng = (const float*)d_in[16];
    const float* ppl_bnb = (const float*)d_in[17];
    const float* ppl_bnm = (const float*)d_in[18];
    const float* ppl_bnv = (const float*)d_in[19];
    const float* proj_w  = (const float*)d_in[20];
    const float* proj_b  = (const float*)d_in[21];
    const float* pbn_g   = (const float*)d_in[22];
    const float* pbn_b   = (const float*)d_in[23];
    const float* pbn_m   = (const float*)d_in[24];
    const float* pbn_v   = (const float*)d_in[25];
    float* out = (float*)d_out;

    cudaFuncSetAttribute(k_attn, cudaFuncAttributeMaxDynamicSharedMemorySize, 65536);

    k_conv<<<dim3(16, 64, 8), 64>>>(x, conv_w, conv_b, bn_g, bn_b, bn_m, bn_v);
    k_qkv<<<dim3(4096, 4, 2), 64>>>(q_w, q_b, k_w, k_b, v_w, v_b);
    k_attn<<<dim3(128, 4, 2), 256, 65536>>>(attn_g);
    k_pool<<<dim3(64, 64, 8), 256>>>(ppl_w, ppl_b, ppl_bng, ppl_bnb, ppl_bnm, ppl_bnv);
    k_upsample<<<dim3(64, 64, 2), 64>>>();
    k_proj<<<8192, 64>>>(proj_w, proj_b, pbn_g, pbn_b, pbn_m, pbn_v, out);
}

// round 2
// speedup vs baseline: 2.7857x; 2.7857x over previous
#include <cuda_runtime.h>
#include <cuda_bf16.h>
#include <math.h>
#include <stdint.h>

#define NB 4
#define BATCH 2
#define HW 4096
#define F 64
#define CF 320

// ---------------- scratch (device globals; no allocation allowed) ----------
__device__ float    g_fused[BATCH * HW * CF];        // [b][pos][320]
__device__ float    g_q[BATCH * NB * HW * 8];        // [bb][pos][8]
__device__ float    g_k[BATCH * NB * HW * 8];
__device__ uint32_t g_vp[BATCH * NB * (HW / 2) * 64]; // paired bf16x2: (V[2kp][c], V[2kp+1][c])
__device__ float    g_pool[NB * BATCH * HW * 16];

// ---------------- mma helpers ----------------------------------------------
__device__ __forceinline__ uint32_t f2tf32(float f) {
    uint32_t r; asm("cvt.rna.tf32.f32 %0, %1;" : "=r"(r) : "f"(f)); return r;
}
__device__ __forceinline__ uint32_t packbf(float hi, float lo) {
    uint32_t r; asm("cvt.rn.bf16x2.f32 %0, %1, %2;" : "=r"(r) : "f"(hi), "f"(lo)); return r;
}
__device__ __forceinline__ void mma_tf32(float c[4], uint32_t a0, uint32_t a1,
                                         uint32_t a2, uint32_t a3,
                                         uint32_t b0, uint32_t b1) {
    asm volatile(
        "mma.sync.aligned.m16n8k8.row.col.f32.tf32.tf32.f32 "
        "{%0,%1,%2,%3},{%4,%5,%6,%7},{%8,%9},{%0,%1,%2,%3};"
        : "+f"(c[0]), "+f"(c[1]), "+f"(c[2]), "+f"(c[3])
        : "r"(a0), "r"(a1), "r"(a2), "r"(a3), "r"(b0), "r"(b1));
}
__device__ __forceinline__ void mma_bf16(float c[4], uint32_t a0, uint32_t a1,
                                         uint32_t a2, uint32_t a3,
                                         uint32_t b0, uint32_t b1) {
    asm volatile(
        "mma.sync.aligned.m16n8k16.row.col.f32.bf16.bf16.f32 "
        "{%0,%1,%2,%3},{%4,%5,%6,%7},{%8,%9},{%0,%1,%2,%3};"
        : "+f"(c[0]), "+f"(c[1]), "+f"(c[2]), "+f"(c[3])
        : "r"(a0), "r"(a1), "r"(a2), "r"(a3), "r"(b0), "r"(b1));
}

// ---------------- K1: dilated 3x3 conv + BN + ReLU -> fused[.., br*64..] ---
__global__ void k_conv(const float* __restrict__ x, const float* __restrict__ w,
                       const float* __restrict__ cb, const float* __restrict__ bg,
                       const float* __restrict__ bbe, const float* __restrict__ bm,
                       const float* __restrict__ bv) {
    int co = threadIdx.x;
    int x0 = blockIdx.x * 4, y = blockIdx.y;
    int b = blockIdx.z >> 2, br = blockIdx.z & 3;
    int d = 1 << br;
    float a0 = 0.f, a1 = 0.f, a2 = 0.f, a3 = 0.f;
    const float* wb = w + br * 9 * 64 * 64 + co;
#pragma unroll
    for (int ky = 0; ky < 3; ++ky) {
        int iy = y + d * (ky - 1);
        if ((unsigned)iy >= 64u) continue;
        const float* xr = x + ((b * 64 + iy) * 64) * 64;
#pragma unroll
        for (int kx = 0; kx < 3; ++kx) {
            int ix = x0 + d * (kx - 1);
            const float* wp = wb + (ky * 3 + kx) * 64 * 64;
            bool v0 = (unsigned)ix < 64u;
            bool v1 = (unsigned)(ix + 1) < 64u;
            bool v2 = (unsigned)(ix + 2) < 64u;
            bool v3 = (unsigned)(ix + 3) < 64u;
            const float* xp = xr + ix * 64;
            float4 z4 = make_float4(0.f, 0.f, 0.f, 0.f);
#pragma unroll 4
            for (int ci = 0; ci < 64; ci += 4) {
                float4 q0 = v0 ? *(const float4*)(xp + ci) : z4;
                float4 q1 = v1 ? *(const float4*)(xp + 64 + ci) : z4;
                float4 q2 = v2 ? *(const float4*)(xp + 128 + ci) : z4;
                float4 q3 = v3 ? *(const float4*)(xp + 192 + ci) : z4;
                float w0 = wp[(ci + 0) * 64], w1 = wp[(ci + 1) * 64];
                float w2 = wp[(ci + 2) * 64], w3 = wp[(ci + 3) * 64];
                a0 += q0.x * w0 + q0.y * w1 + q0.z * w2 + q0.w * w3;
                a1 += q1.x * w0 + q1.y * w1 + q1.z * w2 + q1.w * w3;
                a2 += q2.x * w0 + q2.y * w1 + q2.z * w2 + q2.w * w3;
                a3 += q3.x * w0 + q3.y * w1 + q3.z * w2 + q3.w * w3;
            }
        }
    }
    int idx = br * 64 + co;
    float bias = cb[idx];
    float sc = bg[idx] * rsqrtf(bv[idx] + 1e-3f);
    float sh = bbe[idx] - bm[idx] * sc;
    float* f = g_fused + ((size_t)(b * HW) + y * 64 + x0) * CF + br * 64 + co;
    f[0]      = fmaxf((a0 + bias) * sc + sh, 0.f);
    f[CF]     = fmaxf((a1 + bias) * sc + sh, 0.f);
    f[2 * CF] = fmaxf((a2 + bias) * sc + sh, 0.f);
    f[3 * CF] = fmaxf((a3 + bias) * sc + sh, 0.f);
}

// ---------------- K2: 1x1 convs -> q,k fp32; v paired bf16 -----------------
__global__ void k_qkv(const float* __restrict__ qw, const float* __restrict__ qb,
                      const float* __restrict__ kw, const float* __restrict__ kb_,
                      const float* __restrict__ vw, const float* __restrict__ vb) {
    __shared__ float bs[4][64];
    int t = threadIdx.x, ty = threadIdx.y;
    int n = blockIdx.x * 4 + ty, br = blockIdx.y, b = blockIdx.z;
    bs[ty][t] = g_fused[((size_t)(b * HW + n)) * CF + br * 64 + t];
    __syncthreads();
    int bb = b * NB + br;
    const float* B = bs[ty];
    {
        const float* wv = vw + br * 4096 + t;
        float a = vb[br * 64 + t];
#pragma unroll 8
        for (int ci = 0; ci < 64; ++ci) a += B[ci] * wv[ci * 64];
        __nv_bfloat16* vout = (__nv_bfloat16*)g_vp;
        vout[((size_t)bb * (HW / 2) + (n >> 1)) * 128 + t * 2 + (n & 1)] = __float2bfloat16(a);
    }
    if (t < 16) {
        int dd = t & 7;
        const float* wq = (t < 8 ? qw : kw) + br * 512 + dd;
        float aq = (t < 8 ? qb : kb_)[br * 8 + dd];
#pragma unroll 8
        for (int ci = 0; ci < 64; ++ci) aq += B[ci] * wq[ci * 8];
        (t < 8 ? g_q : g_k)[((size_t)bb * HW + n) * 8 + dd] = aq;
    }
}

// ---------------- K3: flash attention on mma.sync --------------------------
// BM=128 queries/CTA (8 warps x 16 rows), BN=128 keys per tile.
// QK^T: tf32 m16n8k8 (dk=8 exact).  P*V: bf16 m16n8k16, fp32 accum.
__global__ void __launch_bounds__(256) k_attn(const float* __restrict__ gamma) {
    __shared__ float Qs[128 * 8];
    __shared__ float Ks[128 * 8];
    __shared__ uint32_t Vs[128 * 33];   // fragment-order V, pad 33 => conflict-free
    int tid = threadIdx.x;
    int br = blockIdx.y, b = blockIdx.z;
    int bb = b * NB + br;
    int n0 = blockIdx.x * 128;
    int w = tid >> 5, lane = tid & 31;
    int g = lane >> 2, t = lane & 3;

    ((float4*)Qs)[tid] = ((const float4*)(g_q + ((size_t)bb * HW + n0) * 8))[tid];
    __syncthreads();
    int r0i = w * 16 + g;
    uint32_t qa0 = f2tf32(Qs[r0i * 8 + t]);
    uint32_t qa1 = f2tf32(Qs[(r0i + 8) * 8 + t]);
    uint32_t qa2 = f2tf32(Qs[r0i * 8 + t + 4]);
    uint32_t qa3 = f2tf32(Qs[(r0i + 8) * 8 + t + 4]);

    float o[8][4];
#pragma unroll
    for (int nb = 0; nb < 8; ++nb) { o[nb][0] = o[nb][1] = o[nb][2] = o[nb][3] = 0.f; }
    float m0 = -1e30f, m1 = -1e30f, Z0 = 0.f, Z1 = 0.f;

    const float4* kg = (const float4*)(g_k + (size_t)bb * HW * 8);
    const uint32_t* vg = g_vp + (size_t)bb * (HW / 2) * 64;

    for (int kv0 = 0; kv0 < HW; kv0 += 128) {
        __syncthreads();
        ((float4*)Ks)[tid] = kg[kv0 * 2 + tid];
        const uint32_t* vp = vg + (kv0 >> 1) * 64;
#pragma unroll
        for (int it = 0; it < 16; ++it) {
            int i = tid + it * 256;
            uint32_t val = vp[i];
            int kp = i >> 6, c = i & 63;
            Vs[((kp >> 2) * 8 + (c >> 3)) * 33 + (c & 7) * 4 + (kp & 3)] = val;
        }
        __syncthreads();

        // ---- S = Q K^T (tf32), per-warp band 16x128 ----
        float s[16][4];
#pragma unroll
        for (int nb = 0; nb < 16; ++nb) {
            uint32_t b0 = f2tf32(Ks[(nb * 8 + g) * 8 + t]);
            uint32_t b1 = f2tf32(Ks[(nb * 8 + g) * 8 + t + 4]);
            s[nb][0] = s[nb][1] = s[nb][2] = s[nb][3] = 0.f;
            mma_tf32(s[nb], qa0, qa1, qa2, qa3, b0, b1);
        }
        // ---- online softmax ----
        float r0 = -1e30f, r1 = -1e30f;
#pragma unroll
        for (int nb = 0; nb < 16; ++nb) {
            r0 = fmaxf(r0, fmaxf(s[nb][0], s[nb][1]));
            r1 = fmaxf(r1, fmaxf(s[nb][2], s[nb][3]));
        }
        r0 = fmaxf(r0, __shfl_xor_sync(0xffffffffu, r0, 1));
        r0 = fmaxf(r0, __shfl_xor_sync(0xffffffffu, r0, 2));
        r1 = fmaxf(r1, __shfl_xor_sync(0xffffffffu, r1, 1));
        r1 = fmaxf(r1, __shfl_xor_sync(0xffffffffu, r1, 2));
        float m0n = fmaxf(m0, r0), m1n = fmaxf(m1, r1);
        float sc0 = __expf(m0 - m0n), sc1 = __expf(m1 - m1n);
        m0 = m0n; m1 = m1n;
        Z0 *= sc0; Z1 *= sc1;
#pragma unroll
        for (int nb = 0; nb < 8; ++nb) {
            o[nb][0] *= sc0; o[nb][1] *= sc0; o[nb][2] *= sc1; o[nb][3] *= sc1;
        }
        uint32_t pa[16][2];
#pragma unroll
        for (int j = 0; j < 16; ++j) {
            float p0 = __expf(s[j][0] - m0), p1 = __expf(s[j][1] - m0);
            float p2 = __expf(s[j][2] - m1), p3 = __expf(s[j][3] - m1);
            Z0 += p0 + p1; Z1 += p2 + p3;
            pa[j][0] = packbf(p1, p0);
            pa[j][1] = packbf(p3, p2);
        }
        // ---- O += P V (bf16 mma) ----
#pragma unroll
        for (int ks = 0; ks < 8; ++ks) {
#pragma unroll
            for (int nb = 0; nb < 8; ++nb) {
                uint32_t b0 = Vs[((2 * ks) * 8 + nb) * 33 + lane];
                uint32_t b1 = Vs[((2 * ks + 1) * 8 + nb) * 33 + lane];
                mma_bf16(o[nb], pa[2 * ks][0], pa[2 * ks][1],
                         pa[2 * ks + 1][0], pa[2 * ks + 1][1], b0, b1);
            }
        }
    }
    Z0 += __shfl_xor_sync(0xffffffffu, Z0, 1);
    Z0 += __shfl_xor_sync(0xffffffffu, Z0, 2);
    Z1 += __shfl_xor_sync(0xffffffffu, Z1, 1);
    Z1 += __shfl_xor_sync(0xffffffffu, Z1, 2);
    float ga = gamma[br];
    float i0 = ga / Z0, i1 = ga / Z1;
    float* base0 = g_fused + ((size_t)b * HW + n0 + w * 16 + g) * CF + br * 64 + 2 * t;
    float* base1 = base0 + 8 * CF;
#pragma unroll
    for (int nb = 0; nb < 8; ++nb) {
        float2 v0 = *(float2*)(base0 + nb * 8);
        v0.x += o[nb][0] * i0; v0.y += o[nb][1] * i0;
        *(float2*)(base0 + nb * 8) = v0;
        float2 v1 = *(float2*)(base1 + nb * 8);
        v1.x += o[nb][2] * i1; v1.y += o[nb][3] * i1;
        *(float2*)(base1 + nb * 8) = v1;
    }
}

// ---------------- K4: avg-pool(SAME) + 1x1 conv + BN (compact grid) -------
__global__ void k_pool(const float* __restrict__ pw, const float* __restrict__ pb,
                       const float* __restrict__ pg, const float* __restrict__ pbe,
                       const float* __restrict__ pm, const float* __restrict__ pv) {
    const int HP[4] = {64, 32, 22, 11};
    const int PS[4] = {1, 2, 3, 6};
    const int PLO[4] = {0, 0, 1, 1};
    int b = blockIdx.y;
    int lin = blockIdx.x;
    int j, r;
    if (lin < 4096)      { j = 0; r = lin; }
    else if (lin < 5120) { j = 1; r = lin - 4096; }
    else if (lin < 5604) { j = 2; r = lin - 5120; }
    else                 { j = 3; r = lin - 5604; }
    int hp = HP[j], ps = PS[j], plo = PLO[j];
    int oy = r / hp, ox = r % hp;
    __shared__ float avg[256];
    __shared__ float part[256];
    int tt = threadIdx.x;
    int ys = oy * ps - plo, xs = ox * ps - plo;
    int ye = min(ys + ps, 64), xe = min(xs + ps, 64);
    ys = max(ys, 0); xs = max(xs, 0);
    float s = 0.f;
    for (int yy = ys; yy < ye; ++yy)
        for (int xx = xs; xx < xe; ++xx)
            s += g_fused[((size_t)(b * HW) + yy * 64 + xx) * CF + tt];
    avg[tt] = s * (1.f / (float)((ye - ys) * (xe - xs)));
    __syncthreads();
    int o = tt & 15, ck = tt >> 4;
    const float* wp = pw + j * 256 * 16 + o;
    float a = 0.f;
#pragma unroll
    for (int q = 0; q < 16; ++q) {
        int ci = ck * 16 + q;
        a += avg[ci] * wp[ci * 16];
    }
    part[ck * 16 + o] = a;
    __syncthreads();
    if (tt < 16) {
        float acc = pb[j * 16 + tt];
#pragma unroll
        for (int k2 = 0; k2 < 16; ++k2) acc += part[k2 * 16 + tt];
        int idx = j * 16 + tt;
        float sc = pg[idx] * rsqrtf(pv[idx] + 1e-3f);
        float sh = pbe[idx] - pm[idx] * sc;
        g_pool[((size_t)((j * 2 + b) * HW) + oy * hp + ox) * 16 + tt] = acc * sc + sh;
    }
}

// ---------------- K5: bilinear upsample (half-pixel, edge clamp) ----------
__global__ void k_upsample() {
    const int HP[4] = {64, 32, 22, 11};
    int ox = blockIdx.x, oy = blockIdx.y, b = blockIdx.z;
    int t = threadIdx.x;
    int j = t >> 4, c = t & 15;
    int hp = HP[j];
    float scale = hp * (1.f / 64.f);
    float fy = (oy + 0.5f) * scale - 0.5f;
    float fx = (ox + 0.5f) * scale - 0.5f;
    float y0f = floorf(fy), x0f = floorf(fx);
    float ty = fy - y0f, tx = fx - x0f;
    int y0 = min(max((int)y0f, 0), hp - 1);
    int y1 = min(max((int)y0f + 1, 0), hp - 1);
    int xA = min(max((int)x0f, 0), hp - 1);
    int xB = min(max((int)x0f + 1, 0), hp - 1);
    const float* P = g_pool + (size_t)((j * 2 + b) * HW) * 16 + c;
    float v00 = P[(y0 * hp + xA) * 16], v01 = P[(y0 * hp + xB) * 16];
    float v10 = P[(y1 * hp + xA) * 16], v11 = P[(y1 * hp + xB) * 16];
    float val = (1.f - ty) * ((1.f - tx) * v00 + tx * v01)
              + ty * ((1.f - tx) * v10 + tx * v11);
    g_fused[((size_t)(b * HW) + oy * 64 + ox) * CF + 256 + t] = val;
}

// ---------------- K6: 1x1 proj (320->64) + BN + ReLU -> out ---------------
__global__ void k_proj(const float* __restrict__ w, const float* __restrict__ pb,
                       const float* __restrict__ g, const float* __restrict__ be,
                       const float* __restrict__ m, const float* __restrict__ v,
                       float* __restrict__ out) {
    __shared__ float fv[CF];
    int tok = blockIdx.x;
    int t = threadIdx.x;
    for (int i = t; i < CF; i += 64) fv[i] = g_fused[(size_t)tok * CF + i];
    __syncthreads();
    float a = pb[t];
    const float* wp = w + t;
#pragma unroll 8
    for (int ci = 0; ci < CF; ++ci) a += fv[ci] * wp[ci * 64];
    float sc = g[t] * rsqrtf(v[t] + 1e-3f);
    float sh = be[t] - m[t] * sc;
    out[(size_t)tok * 64 + t] = fmaxf(a * sc + sh, 0.f);
}

// ---------------- launch ---------------------------------------------------
extern "C" void kernel_launch(void* const* d_in, const int* in_sizes, int n_in,
                              void* d_out, int out_size) {
    const float* x       = (const float*)d_in[0];
    const float* conv_w  = (const float*)d_in[1];
    const float* conv_b  = (const float*)d_in[2];
    const float* bn_g    = (const float*)d_in[3];
    const float* bn_b    = (const float*)d_in[4];
    const float* bn_m    = (const float*)d_in[5];
    const float* bn_v    = (const float*)d_in[6];
    const float* q_w     = (const float*)d_in[7];
    const float* q_b     = (const float*)d_in[8];
    const float* k_w     = (const float*)d_in[9];
    const float* k_b     = (const float*)d_in[10];
    const float* v_w     = (const float*)d_in[11];
    const float* v_b     = (const float*)d_in[12];
    const float* attn_g  = (const float*)d_in[13];
    const float* ppl_w   = (const float*)d_in[14];
    const float* ppl_b   = (const float*)d_in[15];
    const float* ppl_bng = (const float*)d_in[16];
    const float* ppl_bnb = (const float*)d_in[17];
    const float* ppl_bnm = (const float*)d_in[18];
    const float* ppl_bnv = (const float*)d_in[19];
    const float* proj_w  = (const float*)d_in[20];
    const float* proj_b  = (const float*)d_in[21];
    const float* pbn_g   = (const float*)d_in[22];
    const float* pbn_b   = (const float*)d_in[23];
    const float* pbn_m   = (const float*)d_in[24];
    const float* pbn_v   = (const float*)d_in[25];
    float* out = (float*)d_out;

    k_conv<<<dim3(16, 64, 8), 64>>>(x, conv_w, conv_b, bn_g, bn_b, bn_m, bn_v);
    k_qkv<<<dim3(1024, 4, 2), dim3(64, 4)>>>(q_w, q_b, k_w, k_b, v_w, v_b);
    k_attn<<<dim3(32, 4, 2), 256>>>(attn_g);
    k_pool<<<dim3(5725, 2), 256>>>(ppl_w, ppl_b, ppl_bng, ppl_bnb, ppl_bnm, ppl_bnv);
    k_upsample<<<dim3(64, 64, 2), 64>>>();
    k_proj<<<8192, 64>>>(proj_w, proj_b, pbn_g, pbn_b, pbn_m, pbn_v, out);
}

// round 3
// speedup vs baseline: 4.4464x; 1.5961x over previous
#include <cuda_runtime.h>
#include <cuda_bf16.h>
#include <math.h>
#include <stdint.h>

#define NB 4
#define BATCH 2
#define HW 4096
#define F 64
#define CF 320

// ---------------- scratch (device globals; no allocation allowed) ----------
__device__ float    g_fused[BATCH * HW * CF];        // [b][pos][320]
__device__ float    g_q[BATCH * NB * HW * 8];        // [bb][pos][8]
__device__ float    g_k[BATCH * NB * HW * 8];
__device__ uint32_t g_vp[BATCH * NB * (HW / 2) * 64]; // paired bf16x2
__device__ float    g_pool[NB * BATCH * HW * 16];

// ---------------- mma helpers ----------------------------------------------
__device__ __forceinline__ uint32_t f2tf32(float f) {
    uint32_t r; asm("cvt.rna.tf32.f32 %0, %1;" : "=r"(r) : "f"(f)); return r;
}
__device__ __forceinline__ uint32_t packbf(float hi, float lo) {
    uint32_t r; asm("cvt.rn.bf16x2.f32 %0, %1, %2;" : "=r"(r) : "f"(hi), "f"(lo)); return r;
}
__device__ __forceinline__ void mma_tf32(float c[4], uint32_t a0, uint32_t a1,
                                         uint32_t a2, uint32_t a3,
                                         uint32_t b0, uint32_t b1) {
    asm volatile(
        "mma.sync.aligned.m16n8k8.row.col.f32.tf32.tf32.f32 "
        "{%0,%1,%2,%3},{%4,%5,%6,%7},{%8,%9},{%0,%1,%2,%3};"
        : "+f"(c[0]), "+f"(c[1]), "+f"(c[2]), "+f"(c[3])
        : "r"(a0), "r"(a1), "r"(a2), "r"(a3), "r"(b0), "r"(b1));
}
__device__ __forceinline__ void mma_bf16(float c[4], uint32_t a0, uint32_t a1,
                                         uint32_t a2, uint32_t a3,
                                         uint32_t b0, uint32_t b1) {
    asm volatile(
        "mma.sync.aligned.m16n8k16.row.col.f32.bf16.bf16.f32 "
        "{%0,%1,%2,%3},{%4,%5,%6,%7},{%8,%9},{%0,%1,%2,%3};"
        : "+f"(c[0]), "+f"(c[1]), "+f"(c[2]), "+f"(c[3])
        : "r"(a0), "r"(a1), "r"(a2), "r"(a3), "r"(b0), "r"(b1));
}

// ---------------- K1: dilated 3x3 conv as tf32 implicit GEMM --------------
// CTA: 128 pixels (2 rows) x 64 co. Loop 9 taps, each tap K=64.
// A[128 px][64 ci], W^T[64 co][64 ci], tf32 pre-converted in smem, pad 68.
__global__ void __launch_bounds__(256) k_conv(
        const float* __restrict__ x, const float* __restrict__ wg,
        const float* __restrict__ cb, const float* __restrict__ bg,
        const float* __restrict__ bbe, const float* __restrict__ bm,
        const float* __restrict__ bv) {
    extern __shared__ uint32_t dyn[];
    uint32_t* As = dyn;                    // 128*68
    uint32_t* Wt = dyn + 128 * 68;         // 64*68
    float* scs = (float*)(dyn + 128 * 68 + 64 * 68);
    float* shs = scs + 64;

    int tid = threadIdx.x;
    int bb = blockIdx.y, b = bb >> 2, br = bb & 3;
    int d = 1 << br;
    int pix0 = blockIdx.x * 128;
    int y0 = blockIdx.x * 2;

    if (tid < 64) {
        int idx = br * 64 + tid;
        float sc = bg[idx] * rsqrtf(bv[idx] + 1e-3f);
        scs[tid] = sc;
        shs[tid] = bbe[idx] - bm[idx] * sc + cb[idx] * sc;
    }

    int w = tid >> 5, lane = tid & 31;
    int g = lane >> 2, t = lane & 3;
    int m0 = w * 16;

    float c[8][4];
#pragma unroll
    for (int nb = 0; nb < 8; ++nb) c[nb][0] = c[nb][1] = c[nb][2] = c[nb][3] = 0.f;

    int p = tid >> 1, ch = (tid & 1) * 32;
    int prow = p >> 6, pcol = p & 63;

    const uint32_t* Ar0 = As + (m0 + g) * 68 + t;
    const uint32_t* Ar1 = As + (m0 + g + 8) * 68 + t;
    const uint32_t* Wg_ = Wt + g * 68 + t;

#pragma unroll 1
    for (int tap = 0; tap < 9; ++tap) {
        int ky = tap / 3, kx = tap - ky * 3;
        __syncthreads();
        // ---- load A tile (shifted x, zero fill), cvt to tf32 ----
        {
            int iy = y0 + prow + d * (ky - 1);
            int ix = pcol + d * (kx - 1);
            bool valid = ((unsigned)iy < 64u) & ((unsigned)ix < 64u);
            const float4* src = (const float4*)(x + (((size_t)(b * 64 + iy) * 64 + ix) * 64 + ch));
            uint4* dst = (uint4*)(As + p * 68 + ch);
#pragma unroll
            for (int i = 0; i < 8; ++i) {
                float4 v = valid ? src[i] : make_float4(0.f, 0.f, 0.f, 0.f);
                uint4 u;
                u.x = f2tf32(v.x); u.y = f2tf32(v.y);
                u.z = f2tf32(v.z); u.w = f2tf32(v.w);
                dst[i] = u;
            }
        }
        // ---- load W tap, transpose to [co][ci], cvt ----
        {
            const float* wtap = wg + ((size_t)(br * 9 + tap)) * 4096;
#pragma unroll
            for (int i = 0; i < 4; ++i) {
                int id = tid + i * 256;
                int ci = id >> 4, co4 = (id & 15) * 4;
                float4 v = *(const float4*)(wtap + ci * 64 + co4);
                Wt[(co4 + 0) * 68 + ci] = f2tf32(v.x);
                Wt[(co4 + 1) * 68 + ci] = f2tf32(v.y);
                Wt[(co4 + 2) * 68 + ci] = f2tf32(v.z);
                Wt[(co4 + 3) * 68 + ci] = f2tf32(v.w);
            }
        }
        __syncthreads();
        // ---- mma: M16 x N64 x K64 per warp ----
#pragma unroll
        for (int k0 = 0; k0 < 64; k0 += 8) {
            uint32_t a0 = Ar0[k0], a1 = Ar1[k0];
            uint32_t a2 = Ar0[k0 + 4], a3 = Ar1[k0 + 4];
#pragma unroll
            for (int nb = 0; nb < 8; ++nb) {
                uint32_t b0 = Wg_[nb * 8 * 68 + k0];
                uint32_t b1 = Wg_[nb * 8 * 68 + k0 + 4];
                mma_tf32(c[nb], a0, a1, a2, a3, b0, b1);
            }
        }
    }
    // ---- epilogue: BN + ReLU -> g_fused ----
    float* f0 = g_fused + ((size_t)b * HW + pix0 + m0 + g) * CF + br * 64;
    float* f1 = f0 + 8 * CF;
#pragma unroll
    for (int nb = 0; nb < 8; ++nb) {
        int col = nb * 8 + 2 * t;
        float2 r0, r1;
        r0.x = fmaxf(c[nb][0] * scs[col] + shs[col], 0.f);
        r0.y = fmaxf(c[nb][1] * scs[col + 1] + shs[col + 1], 0.f);
        r1.x = fmaxf(c[nb][2] * scs[col] + shs[col], 0.f);
        r1.y = fmaxf(c[nb][3] * scs[col + 1] + shs[col + 1], 0.f);
        *(float2*)(f0 + col) = r0;
        *(float2*)(f1 + col) = r1;
    }
}

// ---------------- K2: 1x1 convs -> q,k fp32; v paired bf16 -----------------
// 16 positions/block; each thread handles 4 positions per weight load.
__global__ void k_qkv(const float* __restrict__ qw, const float* __restrict__ qb,
                      const float* __restrict__ kw, const float* __restrict__ kb_,
                      const float* __restrict__ vw, const float* __restrict__ vb) {
    __shared__ float bs[16][64];
    int t = threadIdx.x, ty = threadIdx.y;
    int tid = t + ty * 64;
    int n0 = blockIdx.x * 16, br = blockIdx.y, b = blockIdx.z;
    {
        int row = tid >> 4, c4 = (tid & 15) * 4;
        *(float4*)&bs[row][c4] =
            *(const float4*)(g_fused + ((size_t)(b * HW + n0 + row)) * CF + br * 64 + c4);
    }
    __syncthreads();
    int bb = b * NB + br;
    int r0 = ty * 4;
    {
        const float* wv = vw + br * 4096 + t;
        float vb0 = vb[br * 64 + t];
        float a0 = vb0, a1 = vb0, a2 = vb0, a3 = vb0;
#pragma unroll 8
        for (int ci = 0; ci < 64; ++ci) {
            float wt = wv[ci * 64];
            a0 += bs[r0][ci] * wt;
            a1 += bs[r0 + 1][ci] * wt;
            a2 += bs[r0 + 2][ci] * wt;
            a3 += bs[r0 + 3][ci] * wt;
        }
        __nv_bfloat16* vout = (__nv_bfloat16*)g_vp;
        int n = n0 + r0;
        vout[((size_t)bb * (HW / 2) + ((n + 0) >> 1)) * 128 + t * 2 + ((n + 0) & 1)] = __float2bfloat16(a0);
        vout[((size_t)bb * (HW / 2) + ((n + 1) >> 1)) * 128 + t * 2 + ((n + 1) & 1)] = __float2bfloat16(a1);
        vout[((size_t)bb * (HW / 2) + ((n + 2) >> 1)) * 128 + t * 2 + ((n + 2) & 1)] = __float2bfloat16(a2);
        vout[((size_t)bb * (HW / 2) + ((n + 3) >> 1)) * 128 + t * 2 + ((n + 3) & 1)] = __float2bfloat16(a3);
    }
    if (t < 16) {
        int dd = t & 7;
        const float* wq = (t < 8 ? qw : kw) + br * 512 + dd;
        float bias = (t < 8 ? qb : kb_)[br * 8 + dd];
        float a0 = bias, a1 = bias, a2 = bias, a3 = bias;
#pragma unroll 8
        for (int ci = 0; ci < 64; ++ci) {
            float wt = wq[ci * 8];
            a0 += bs[r0][ci] * wt;
            a1 += bs[r0 + 1][ci] * wt;
            a2 += bs[r0 + 2][ci] * wt;
            a3 += bs[r0 + 3][ci] * wt;
        }
        float* dst = (t < 8 ? g_q : g_k) + ((size_t)bb * HW + n0 + r0) * 8 + dd;
        dst[0] = a0; dst[8] = a1; dst[16] = a2; dst[24] = a3;
    }
}

// ---------------- K3: flash attention on mma.sync --------------------------
__global__ void __launch_bounds__(256) k_attn(const float* __restrict__ gamma) {
    __shared__ float Qs[128 * 8];
    __shared__ float Ks[128 * 8];
    __shared__ uint32_t Vs[128 * 33];
    int tid = threadIdx.x;
    int br = blockIdx.y, b = blockIdx.z;
    int bb = b * NB + br;
    int n0 = blockIdx.x * 128;
    int w = tid >> 5, lane = tid & 31;
    int g = lane >> 2, t = lane & 3;

    ((float4*)Qs)[tid] = ((const float4*)(g_q + ((size_t)bb * HW + n0) * 8))[tid];
    __syncthreads();
    int r0i = w * 16 + g;
    uint32_t qa0 = f2tf32(Qs[r0i * 8 + t]);
    uint32_t qa1 = f2tf32(Qs[(r0i + 8) * 8 + t]);
    uint32_t qa2 = f2tf32(Qs[r0i * 8 + t + 4]);
    uint32_t qa3 = f2tf32(Qs[(r0i + 8) * 8 + t + 4]);

    float o[8][4];
#pragma unroll
    for (int nb = 0; nb < 8; ++nb) { o[nb][0] = o[nb][1] = o[nb][2] = o[nb][3] = 0.f; }
    float m0 = -1e30f, m1 = -1e30f, Z0 = 0.f, Z1 = 0.f;

    const float4* kg = (const float4*)(g_k + (size_t)bb * HW * 8);
    const uint32_t* vg = g_vp + (size_t)bb * (HW / 2) * 64;

    for (int kv0 = 0; kv0 < HW; kv0 += 128) {
        __syncthreads();
        ((float4*)Ks)[tid] = kg[kv0 * 2 + tid];
        const uint32_t* vp = vg + (kv0 >> 1) * 64;
#pragma unroll
        for (int it = 0; it < 16; ++it) {
            int i = tid + it * 256;
            uint32_t val = vp[i];
            int kp = i >> 6, cc = i & 63;
            Vs[((kp >> 2) * 8 + (cc >> 3)) * 33 + (cc & 7) * 4 + (kp & 3)] = val;
        }
        __syncthreads();

        float s[16][4];
#pragma unroll
        for (int nb = 0; nb < 16; ++nb) {
            uint32_t b0 = f2tf32(Ks[(nb * 8 + g) * 8 + t]);
            uint32_t b1 = f2tf32(Ks[(nb * 8 + g) * 8 + t + 4]);
            s[nb][0] = s[nb][1] = s[nb][2] = s[nb][3] = 0.f;
            mma_tf32(s[nb], qa0, qa1, qa2, qa3, b0, b1);
        }
        float r0 = -1e30f, r1 = -1e30f;
#pragma unroll
        for (int nb = 0; nb < 16; ++nb) {
            r0 = fmaxf(r0, fmaxf(s[nb][0], s[nb][1]));
            r1 = fmaxf(r1, fmaxf(s[nb][2], s[nb][3]));
        }
        r0 = fmaxf(r0, __shfl_xor_sync(0xffffffffu, r0, 1));
        r0 = fmaxf(r0, __shfl_xor_sync(0xffffffffu, r0, 2));
        r1 = fmaxf(r1, __shfl_xor_sync(0xffffffffu, r1, 1));
        r1 = fmaxf(r1, __shfl_xor_sync(0xffffffffu, r1, 2));
        float m0n = fmaxf(m0, r0), m1n = fmaxf(m1, r1);
        float sc0 = __expf(m0 - m0n), sc1 = __expf(m1 - m1n);
        m0 = m0n; m1 = m1n;
        Z0 *= sc0; Z1 *= sc1;
#pragma unroll
        for (int nb = 0; nb < 8; ++nb) {
            o[nb][0] *= sc0; o[nb][1] *= sc0; o[nb][2] *= sc1; o[nb][3] *= sc1;
        }
        uint32_t pa[16][2];
#pragma unroll
        for (int j = 0; j < 16; ++j) {
            float p0 = __expf(s[j][0] - m0), p1 = __expf(s[j][1] - m0);
            float p2 = __expf(s[j][2] - m1), p3 = __expf(s[j][3] - m1);
            Z0 += p0 + p1; Z1 += p2 + p3;
            pa[j][0] = packbf(p1, p0);
            pa[j][1] = packbf(p3, p2);
        }
#pragma unroll
        for (int ks = 0; ks < 8; ++ks) {
#pragma unroll
            for (int nb = 0; nb < 8; ++nb) {
                uint32_t b0 = Vs[((2 * ks) * 8 + nb) * 33 + lane];
                uint32_t b1 = Vs[((2 * ks + 1) * 8 + nb) * 33 + lane];
                mma_bf16(o[nb], pa[2 * ks][0], pa[2 * ks][1],
                         pa[2 * ks + 1][0], pa[2 * ks + 1][1], b0, b1);
            }
        }
    }
    Z0 += __shfl_xor_sync(0xffffffffu, Z0, 1);
    Z0 += __shfl_xor_sync(0xffffffffu, Z0, 2);
    Z1 += __shfl_xor_sync(0xffffffffu, Z1, 1);
    Z1 += __shfl_xor_sync(0xffffffffu, Z1, 2);
    float ga = gamma[br];
    float i0 = ga / Z0, i1 = ga / Z1;
    float* base0 = g_fused + ((size_t)b * HW + n0 + w * 16 + g) * CF + br * 64 + 2 * t;
    float* base1 = base0 + 8 * CF;
#pragma unroll
    for (int nb = 0; nb < 8; ++nb) {
        float2 v0 = *(float2*)(base0 + nb * 8);
        v0.x += o[nb][0] * i0; v0.y += o[nb][1] * i0;
        *(float2*)(base0 + nb * 8) = v0;
        float2 v1 = *(float2*)(base1 + nb * 8);
        v1.x += o[nb][2] * i1; v1.y += o[nb][3] * i1;
        *(float2*)(base1 + nb * 8) = v1;
    }
}

// ---------------- K4a: ps=1 pyramid level: 1x1 conv 256->16 + BN ----------
__global__ void k_pool0(const float* __restrict__ pw, const float* __restrict__ pb,
                        const float* __restrict__ pg, const float* __restrict__ pbe,
                        const float* __restrict__ pm, const float* __restrict__ pv) {
    __shared__ float av[16][256];
    __shared__ float ws[256 * 16];
    int tid = threadIdx.x;
    int px0 = blockIdx.x * 16, b = blockIdx.y;
#pragma unroll
    for (int i = 0; i < 4; ++i) {
        int fid = tid + i * 256;
        int px = fid >> 6, c4 = (fid & 63) * 4;
        *(float4*)&av[px][c4] =
            *(const float4*)(g_fused + ((size_t)(b * HW + px0 + px)) * CF + c4);
        *(float4*)&ws[fid * 4] = *(const float4*)(pw + fid * 4);
    }
    __syncthreads();
    int o = tid & 15, px = tid >> 4;
    float acc = pb[o];
#pragma unroll 8
    for (int ci = 0; ci < 256; ++ci) acc += av[px][ci] * ws[ci * 16 + o];
    float sc = pg[o] * rsqrtf(pv[o] + 1e-3f);
    float sh = pbe[o] - pm[o] * sc;
    g_fused[((size_t)(b * HW + px0 + px)) * CF + 256 + o] = acc * sc + sh;
}

// ---------------- K4b: ps>=2 avg-pool(SAME) + 1x1 conv + BN ---------------
__global__ void k_pool(const float* __restrict__ pw, const float* __restrict__ pb,
                       const float* __restrict__ pg, const float* __restrict__ pbe,
                       const float* __restrict__ pm, const float* __restrict__ pv) {
    const int HP[4] = {64, 32, 22, 11};
    const int PS[4] = {1, 2, 3, 6};
    const int PLO[4] = {0, 0, 1, 1};
    int b = blockIdx.y;
    int lin = blockIdx.x;
    int j, r;
    if (lin < 1024)      { j = 1; r = lin; }
    else if (lin < 1508) { j = 2; r = lin - 1024; }
    else                 { j = 3; r = lin - 1508; }
    int hp = HP[j], ps = PS[j], plo = PLO[j];
    int oy = r / hp, ox = r % hp;
    __shared__ float avg[256];
    __shared__ float part[256];
    int tt = threadIdx.x;
    int ys = oy * ps - plo, xs = ox * ps - plo;
    int ye = min(ys + ps, 64), xe = min(xs + ps, 64);
    ys = max(ys, 0); xs = max(xs, 0);
    float s = 0.f;
    for (int yy = ys; yy < ye; ++yy)
        for (int xx = xs; xx < xe; ++xx)
            s += g_fused[((size_t)(b * HW) + yy * 64 + xx) * CF + tt];
    avg[tt] = s * (1.f / (float)((ye - ys) * (xe - xs)));
    __syncthreads();
    int o = tt & 15, ck = tt >> 4;
    const float* wp = pw + j * 256 * 16 + o;
    float a = 0.f;
#pragma unroll
    for (int q = 0; q < 16; ++q) {
        int ci = ck * 16 + q;
        a += avg[ci] * wp[ci * 16];
    }
    part[ck * 16 + o] = a;
    __syncthreads();
    if (tt < 16) {
        float acc = pb[j * 16 + tt];
#pragma unroll
        for (int k2 = 0; k2 < 16; ++k2) acc += part[k2 * 16 + tt];
        int idx = j * 16 + tt;
        float sc = pg[idx] * rsqrtf(pv[idx] + 1e-3f);
        float sh = pbe[idx] - pm[idx] * sc;
        g_pool[((size_t)((j * 2 + b) * HW) + oy * hp + ox) * 16 + tt] = acc * sc + sh;
    }
}

// ---------------- K5: bilinear upsample (ps>=2 levels, 48 ch) --------------
__global__ void k_upsample() {
    const int HP[4] = {64, 32, 22, 11};
    int ox = blockIdx.x, oy = blockIdx.y, b = blockIdx.z;
    int t = threadIdx.x;
    int j = (t >> 4) + 1, c = t & 15;
    int hp = HP[j];
    float scale = hp * (1.f / 64.f);
    float fy = (oy + 0.5f) * scale - 0.5f;
    float fx = (ox + 0.5f) * scale - 0.5f;
    float y0f = floorf(fy), x0f = floorf(fx);
    float ty = fy - y0f, tx = fx - x0f;
    int y0 = min(max((int)y0f, 0), hp - 1);
    int y1 = min(max((int)y0f + 1, 0), hp - 1);
    int xA = min(max((int)x0f, 0), hp - 1);
    int xB = min(max((int)x0f + 1, 0), hp - 1);
    const float* P = g_pool + (size_t)((j * 2 + b) * HW) * 16 + c;
    float v00 = P[(y0 * hp + xA) * 16], v01 = P[(y0 * hp + xB) * 16];
    float v10 = P[(y1 * hp + xA) * 16], v11 = P[(y1 * hp + xB) * 16];
    float val = (1.f - ty) * ((1.f - tx) * v00 + tx * v01)
              + ty * ((1.f - tx) * v10 + tx * v11);
    g_fused[((size_t)(b * HW) + oy * 64 + ox) * CF + 256 + 16 + t] = val;
}

// ---------------- K6: 1x1 proj (320->64) + BN + ReLU, 16 tokens/block -----
__global__ void k_proj(const float* __restrict__ w, const float* __restrict__ pb,
                       const float* __restrict__ g, const float* __restrict__ be,
                       const float* __restrict__ m, const float* __restrict__ v,
                       float* __restrict__ out) {
    __shared__ float fv[16][CF];
    int tid = threadIdx.x;
    int tok0 = blockIdx.x * 16;
#pragma unroll
    for (int i = 0; i < 5; ++i) {
        int fid = tid + i * 256;
        int px = fid / 80, c4 = (fid % 80) * 4;
        *(float4*)&fv[px][c4] = *(const float4*)(g_fused + (size_t)(tok0 + px) * CF + c4);
    }
    __syncthreads();
    int co = tid & 63, tg = tid >> 6;
    int r0 = tg * 4;
    float a0 = pb[co], a1 = a0, a2 = a0, a3 = a0;
    const float* wp = w + co;
#pragma unroll 8
    for (int ci = 0; ci < CF; ++ci) {
        float wt = wp[ci * 64];
        a0 += fv[r0][ci] * wt;
        a1 += fv[r0 + 1][ci] * wt;
        a2 += fv[r0 + 2][ci] * wt;
        a3 += fv[r0 + 3][ci] * wt;
    }
    float sc = g[co] * rsqrtf(v[co] + 1e-3f);
    float sh = be[co] - m[co] * sc;
    float* op = out + (size_t)(tok0 + r0) * 64 + co;
    op[0]   = fmaxf(a0 * sc + sh, 0.f);
    op[64]  = fmaxf(a1 * sc + sh, 0.f);
    op[128] = fmaxf(a2 * sc + sh, 0.f);
    op[192] = fmaxf(a3 * sc + sh, 0.f);
}

// ---------------- launch ---------------------------------------------------
extern "C" void kernel_launch(void* const* d_in, const int* in_sizes, int n_in,
                              void* d_out, int out_size) {
    const float* x       = (const float*)d_in[0];
    const float* conv_w  = (const float*)d_in[1];
    const float* conv_b  = (const float*)d_in[2];
    const float* bn_g    = (const float*)d_in[3];
    const float* bn_b    = (const float*)d_in[4];
    const float* bn_m    = (const float*)d_in[5];
    const float* bn_v    = (const float*)d_in[6];
    const float* q_w     = (const float*)d_in[7];
    const float* q_b     = (const float*)d_in[8];
    const float* k_w     = (const float*)d_in[9];
    const float* k_b     = (const float*)d_in[10];
    const float* v_w     = (const float*)d_in[11];
    const float* v_b     = (const float*)d_in[12];
    const float* attn_g  = (const float*)d_in[13];
    const float* ppl_w   = (const float*)d_in[14];
    const float* ppl_b   = (const float*)d_in[15];
    const float* ppl_bng = (const float*)d_in[16];
    const float* ppl_bnb = (const float*)d_in[17];
    const float* ppl_bnm = (const float*)d_in[18];
    const float* ppl_bnv = (const float*)d_in[19];
    const float* proj_w  = (const float*)d_in[20];
    const float* proj_b  = (const float*)d_in[21];
    const float* pbn_g   = (const float*)d_in[22];
    const float* pbn_b   = (const float*)d_in[23];
    const float* pbn_m   = (const float*)d_in[24];
    const float* pbn_v   = (const float*)d_in[25];
    float* out = (float*)d_out;

    const int CONV_SMEM = (128 * 68 + 64 * 68 + 128) * 4;  // 52,736 B
    cudaFuncSetAttribute(k_conv, cudaFuncAttributeMaxDynamicSharedMemorySize, CONV_SMEM);

    k_conv<<<dim3(32, 8), 256, CONV_SMEM>>>(x, conv_w, conv_b, bn_g, bn_b, bn_m, bn_v);
    k_qkv<<<dim3(256, 4, 2), dim3(64, 4)>>>(q_w, q_b, k_w, k_b, v_w, v_b);
    k_attn<<<dim3(32, 4, 2), 256>>>(attn_g);
    k_pool0<<<dim3(256, 2), 256>>>(ppl_w, ppl_b, ppl_bng, ppl_bnb, ppl_bnm, ppl_bnv);
    k_pool<<<dim3(1629, 2), 256>>>(ppl_w, ppl_b, ppl_bng, ppl_bnb, ppl_bnm, ppl_bnv);
    k_upsample<<<dim3(64, 64, 2), 48>>>();
    k_proj<<<512, 256>>>(proj_w, proj_b, pbn_g, pbn_b, pbn_m, pbn_v, out);
}

// round 5
// speedup vs baseline: 5.1558x; 1.1595x over previous
#include <cuda_runtime.h>
#include <cuda_bf16.h>
#include <math.h>
#include <stdint.h>

#define NB 4
#define BATCH 2
#define HW 4096
#define F 64

// ---------------- scratch (device globals; no allocation allowed) ----------
__device__ float    g_fused[BATCH * HW * 256];        // [b][pos][256]
__device__ uint32_t g_q[BATCH * NB * HW * 8];         // tf32 bits
__device__ uint32_t g_k[BATCH * NB * HW * 8];         // tf32 bits
__device__ uint32_t g_vp[BATCH * NB * (HW / 2) * 64]; // paired bf16x2 [kp][c]
__device__ float    g_pool[NB * BATCH * HW * 16];

// ---------------- mma helpers ----------------------------------------------
__device__ __forceinline__ uint32_t f2tf32(float f) {
    uint32_t r; asm("cvt.rna.tf32.f32 %0, %1;" : "=r"(r) : "f"(f)); return r;
}
__device__ __forceinline__ uint32_t packbf(float hi, float lo) {
    uint32_t r; asm("cvt.rn.bf16x2.f32 %0, %1, %2;" : "=r"(r) : "f"(hi), "f"(lo)); return r;
}
__device__ __forceinline__ void mma_tf32(float c[4], uint32_t a0, uint32_t a1,
                                         uint32_t a2, uint32_t a3,
                                         uint32_t b0, uint32_t b1) {
    asm volatile(
        "mma.sync.aligned.m16n8k8.row.col.f32.tf32.tf32.f32 "
        "{%0,%1,%2,%3},{%4,%5,%6,%7},{%8,%9},{%0,%1,%2,%3};"
        : "+f"(c[0]), "+f"(c[1]), "+f"(c[2]), "+f"(c[3])
        : "r"(a0), "r"(a1), "r"(a2), "r"(a3), "r"(b0), "r"(b1));
}
__device__ __forceinline__ void mma_bf16(float c[4], uint32_t a0, uint32_t a1,
                                         uint32_t a2, uint32_t a3,
                                         uint32_t b0, uint32_t b1) {
    asm volatile(
        "mma.sync.aligned.m16n8k16.row.col.f32.bf16.bf16.f32 "
        "{%0,%1,%2,%3},{%4,%5,%6,%7},{%8,%9},{%0,%1,%2,%3};"
        : "+f"(c[0]), "+f"(c[1]), "+f"(c[2]), "+f"(c[3])
        : "r"(a0), "r"(a1), "r"(a2), "r"(a3), "r"(b0), "r"(b1));
}
__device__ __forceinline__ void ldsm_x4(uint32_t& r0, uint32_t& r1,
                                        uint32_t& r2, uint32_t& r3, uint32_t addr) {
    asm volatile("ldmatrix.sync.aligned.m8n8.x4.shared.b16 {%0,%1,%2,%3}, [%4];"
        : "=r"(r0), "=r"(r1), "=r"(r2), "=r"(r3) : "r"(addr));
}

// ---------------- K1: dilated 3x3 conv as tf32 implicit GEMM --------------
__global__ void __launch_bounds__(256) k_conv(
        const float* __restrict__ x, const float* __restrict__ wg,
        const float* __restrict__ cb, const float* __restrict__ bg,
        const float* __restrict__ bbe, const float* __restrict__ bm,
        const float* __restrict__ bv) {
    extern __shared__ uint32_t dyn[];
    uint32_t* As = dyn;                    // 128*68
    uint32_t* Wt = dyn + 128 * 68;         // 64*68
    float* scs = (float*)(dyn + 128 * 68 + 64 * 68);
    float* shs = scs + 64;

    int tid = threadIdx.x;
    int bb = blockIdx.y, b = bb >> 2, br = bb & 3;
    int d = 1 << br;
    int pix0 = blockIdx.x * 128;
    int y0 = blockIdx.x * 2;

    if (tid < 64) {
        int idx = br * 64 + tid;
        float sc = bg[idx] * rsqrtf(bv[idx] + 1e-3f);
        scs[tid] = sc;
        shs[tid] = bbe[idx] - bm[idx] * sc + cb[idx] * sc;
    }

    int w = tid >> 5, lane = tid & 31;
    int g = lane >> 2, t = lane & 3;
    int m0 = w * 16;

    float c[8][4];
#pragma unroll
    for (int nb = 0; nb < 8; ++nb) c[nb][0] = c[nb][1] = c[nb][2] = c[nb][3] = 0.f;

    int p = tid >> 1, ch = (tid & 1) * 32;
    int prow = p >> 6, pcol = p & 63;

    const uint32_t* Ar0 = As + (m0 + g) * 68 + t;
    const uint32_t* Ar1 = As + (m0 + g + 8) * 68 + t;
    const uint32_t* Wg_ = Wt + g * 68 + t;

#pragma unroll 1
    for (int tap = 0; tap < 9; ++tap) {
        int ky = tap / 3, kx = tap - ky * 3;
        __syncthreads();
        {
            int iy = y0 + prow + d * (ky - 1);
            int ix = pcol + d * (kx - 1);
            bool valid = ((unsigned)iy < 64u) & ((unsigned)ix < 64u);
            const float4* src = (const float4*)(x + (((size_t)(b * 64 + iy) * 64 + ix) * 64 + ch));
            uint4* dst = (uint4*)(As + p * 68 + ch);
#pragma unroll
            for (int i = 0; i < 8; ++i) {
                float4 v = valid ? src[i] : make_float4(0.f, 0.f, 0.f, 0.f);
                uint4 u;
                u.x = f2tf32(v.x); u.y = f2tf32(v.y);
                u.z = f2tf32(v.z); u.w = f2tf32(v.w);
                dst[i] = u;
            }
        }
        {
            const float* wtap = wg + ((size_t)(br * 9 + tap)) * 4096;
#pragma unroll
            for (int i = 0; i < 4; ++i) {
                int id = tid + i * 256;
                int ci = id >> 4, co4 = (id & 15) * 4;
                float4 v = *(const float4*)(wtap + ci * 64 + co4);
                Wt[(co4 + 0) * 68 + ci] = f2tf32(v.x);
                Wt[(co4 + 1) * 68 + ci] = f2tf32(v.y);
                Wt[(co4 + 2) * 68 + ci] = f2tf32(v.z);
                Wt[(co4 + 3) * 68 + ci] = f2tf32(v.w);
            }
        }
        __syncthreads();
#pragma unroll
        for (int k0 = 0; k0 < 64; k0 += 8) {
            uint32_t a0 = Ar0[k0], a1 = Ar1[k0];
            uint32_t a2 = Ar0[k0 + 4], a3 = Ar1[k0 + 4];
#pragma unroll
            for (int nb = 0; nb < 8; ++nb) {
                uint32_t b0 = Wg_[nb * 8 * 68 + k0];
                uint32_t b1 = Wg_[nb * 8 * 68 + k0 + 4];
                mma_tf32(c[nb], a0, a1, a2, a3, b0, b1);
            }
        }
    }
    float* f0 = g_fused + ((size_t)b * HW + pix0 + m0 + g) * 256 + br * 64;
    float* f1 = f0 + 8 * 256;
#pragma unroll
    for (int nb = 0; nb < 8; ++nb) {
        int col = nb * 8 + 2 * t;
        float2 r0, r1;
        r0.x = fmaxf(c[nb][0] * scs[col] + shs[col], 0.f);
        r0.y = fmaxf(c[nb][1] * scs[col + 1] + shs[col + 1], 0.f);
        r1.x = fmaxf(c[nb][2] * scs[col] + shs[col], 0.f);
        r1.y = fmaxf(c[nb][3] * scs[col + 1] + shs[col + 1], 0.f);
        *(float2*)(f0 + col) = r0;
        *(float2*)(f1 + col) = r1;
    }
}

// ---------------- K2: 1x1 convs -> q,k tf32 bits; v paired bf16 ------------
__global__ void k_qkv(const float* __restrict__ qw, const float* __restrict__ qb,
                      const float* __restrict__ kw, const float* __restrict__ kb_,
                      const float* __restrict__ vw, const float* __restrict__ vb) {
    __shared__ float bs[16][64];
    int t = threadIdx.x, ty = threadIdx.y;
    int tid = t + ty * 64;
    int n0 = blockIdx.x * 16, br = blockIdx.y, b = blockIdx.z;
    {
        int row = tid >> 4, c4 = (tid & 15) * 4;
        *(float4*)&bs[row][c4] =
            *(const float4*)(g_fused + ((size_t)(b * HW + n0 + row)) * 256 + br * 64 + c4);
    }
    __syncthreads();
    int bb = b * NB + br;
    int r0 = ty * 4;
    {
        const float* wv = vw + br * 4096 + t;
        float vb0 = vb[br * 64 + t];
        float a0 = vb0, a1 = vb0, a2 = vb0, a3 = vb0;
#pragma unroll 8
        for (int ci = 0; ci < 64; ++ci) {
            float wt = wv[ci * 64];
            a0 += bs[r0][ci] * wt;
            a1 += bs[r0 + 1][ci] * wt;
            a2 += bs[r0 + 2][ci] * wt;
            a3 += bs[r0 + 3][ci] * wt;
        }
        uint32_t* vout = g_vp + (size_t)bb * (HW / 2) * 64;
        int kp = (n0 + r0) >> 1;   // r0 is even
        vout[(size_t)kp * 64 + t]       = packbf(a1, a0);
        vout[(size_t)(kp + 1) * 64 + t] = packbf(a3, a2);
    }
    if (t < 16) {
        int dd = t & 7;
        const float* wq = (t < 8 ? qw : kw) + br * 512 + dd;
        float bias = (t < 8 ? qb : kb_)[br * 8 + dd];
        float a0 = bias, a1 = bias, a2 = bias, a3 = bias;
#pragma unroll 8
        for (int ci = 0; ci < 64; ++ci) {
            float wt = wq[ci * 8];
            a0 += bs[r0][ci] * wt;
            a1 += bs[r0 + 1][ci] * wt;
            a2 += bs[r0 + 2][ci] * wt;
            a3 += bs[r0 + 3][ci] * wt;
        }
        uint32_t* dst = (t < 8 ? g_q : g_k) + ((size_t)bb * HW + n0 + r0) * 8 + dd;
        dst[0] = f2tf32(a0); dst[8] = f2tf32(a1);
        dst[16] = f2tf32(a2); dst[24] = f2tf32(a3);
    }
}

// ---------------- K3: flash attention on mma.sync + ldmatrix ---------------
// V smem: 128 matrices of 8x8 bf16, stride 128 B (no pad): matrix
// mat = (kp>>2)*8 + (c>>3); row = c&7; col = kp&3. Row = 16 B contiguous.
__global__ void __launch_bounds__(256) k_attn(const float* __restrict__ gamma) {
    __shared__ __align__(16) uint32_t Qs[128 * 8];
    __shared__ __align__(16) uint32_t Ks[128 * 8];
    __shared__ __align__(16) uint32_t Vs[128 * 32];
    int tid = threadIdx.x;
    int br = blockIdx.y, b = blockIdx.z;
    int bb = b * NB + br;
    int n0 = blockIdx.x * 128;
    int w = tid >> 5, lane = tid & 31;
    int g = lane >> 2, t = lane & 3;

    ((uint4*)Qs)[tid] = ((const uint4*)(g_q + ((size_t)bb * HW + n0) * 8))[tid];
    __syncthreads();
    int r0i = w * 16 + g;
    uint32_t qa0 = Qs[r0i * 8 + t];
    uint32_t qa1 = Qs[(r0i + 8) * 8 + t];
    uint32_t qa2 = Qs[r0i * 8 + t + 4];
    uint32_t qa3 = Qs[(r0i + 8) * 8 + t + 4];

    // ldmatrix per-lane base: lanes 0-7 -> mat+0, 8-15 -> mat+8, 16-23 -> mat+1, 24-31 -> mat+9
    uint32_t vs_base = (uint32_t)__cvta_generic_to_shared(Vs);
    int midx = lane >> 3;
    int lane_const = (midx & 1) * 8 + (midx >> 1);
    uint32_t lb = vs_base + (uint32_t)((lane_const * 32 + (lane & 7) * 4) * 4);

    float o[8][4];
#pragma unroll
    for (int nb = 0; nb < 8; ++nb) { o[nb][0] = o[nb][1] = o[nb][2] = o[nb][3] = 0.f; }
    float m0 = -1e30f, m1 = -1e30f, Z0 = 0.f, Z1 = 0.f;

    const uint4* kg = (const uint4*)(g_k + (size_t)bb * HW * 8);
    const uint32_t* vg = g_vp + (size_t)bb * (HW / 2) * 64;

    for (int kv0 = 0; kv0 < HW; kv0 += 128) {
        __syncthreads();
        ((uint4*)Ks)[tid] = kg[kv0 * 2 + tid];
        const uint32_t* vp = vg + (kv0 >> 1) * 64;
        // stage V: thread -> one 8x8 matrix row (4 kp-cols) per iter, STS.128
#pragma unroll
        for (int itr = 0; itr < 4; ++itr) {
            int row_lin = tid + itr * 256;               // 0..1023
            int base = (row_lin >> 6) * 256 + (row_lin & 63);
            uint4 u;
            u.x = vp[base];
            u.y = vp[base + 64];
            u.z = vp[base + 128];
            u.w = vp[base + 192];
            ((uint4*)Vs)[row_lin] = u;
        }
        __syncthreads();

        float s[16][4];
#pragma unroll
        for (int nb = 0; nb < 16; ++nb) {
            uint32_t b0 = Ks[(nb * 8 + g) * 8 + t];
            uint32_t b1 = Ks[(nb * 8 + g) * 8 + t + 4];
            s[nb][0] = s[nb][1] = s[nb][2] = s[nb][3] = 0.f;
            mma_tf32(s[nb], qa0, qa1, qa2, qa3, b0, b1);
        }
        float r0 = -1e30f, r1 = -1e30f;
#pragma unroll
        for (int nb = 0; nb < 16; ++nb) {
            r0 = fmaxf(r0, fmaxf(s[nb][0], s[nb][1]));
            r1 = fmaxf(r1, fmaxf(s[nb][2], s[nb][3]));
        }
        r0 = fmaxf(r0, __shfl_xor_sync(0xffffffffu, r0, 1));
        r0 = fmaxf(r0, __shfl_xor_sync(0xffffffffu, r0, 2));
        r1 = fmaxf(r1, __shfl_xor_sync(0xffffffffu, r1, 1));
        r1 = fmaxf(r1, __shfl_xor_sync(0xffffffffu, r1, 2));
        float m0n = fmaxf(m0, r0), m1n = fmaxf(m1, r1);
        float sc0 = __expf(m0 - m0n), sc1 = __expf(m1 - m1n);
        m0 = m0n; m1 = m1n;
        Z0 *= sc0; Z1 *= sc1;
#pragma unroll
        for (int nb = 0; nb < 8; ++nb) {
            o[nb][0] *= sc0; o[nb][1] *= sc0; o[nb][2] *= sc1; o[nb][3] *= sc1;
        }
        uint32_t pa[16][2];
#pragma unroll
        for (int j = 0; j < 16; ++j) {
            float p0 = __expf(s[j][0] - m0), p1 = __expf(s[j][1] - m0);
            float p2 = __expf(s[j][2] - m1), p3 = __expf(s[j][3] - m1);
            Z0 += p0 + p1; Z1 += p2 + p3;
            pa[j][0] = packbf(p1, p0);
            pa[j][1] = packbf(p3, p2);
        }
#pragma unroll
        for (int ks = 0; ks < 8; ++ks) {
#pragma unroll
            for (int nbp = 0; nbp < 4; ++nbp) {
                uint32_t b00, b10, b01, b11;
                ldsm_x4(b00, b10, b01, b11, lb + (uint32_t)((16 * ks + 2 * nbp) * 128));
                mma_bf16(o[2 * nbp], pa[2 * ks][0], pa[2 * ks][1],
                         pa[2 * ks + 1][0], pa[2 * ks + 1][1], b00, b10);
                mma_bf16(o[2 * nbp + 1], pa[2 * ks][0], pa[2 * ks][1],
                         pa[2 * ks + 1][0], pa[2 * ks + 1][1], b01, b11);
            }
        }
    }
    Z0 += __shfl_xor_sync(0xffffffffu, Z0, 1);
    Z0 += __shfl_xor_sync(0xffffffffu, Z0, 2);
    Z1 += __shfl_xor_sync(0xffffffffu, Z1, 1);
    Z1 += __shfl_xor_sync(0xffffffffu, Z1, 2);
    float ga = gamma[br];
    float i0 = ga / Z0, i1 = ga / Z1;
    float* base0 = g_fused + ((size_t)b * HW + n0 + w * 16 + g) * 256 + br * 64 + 2 * t;
    float* base1 = base0 + 8 * 256;
#pragma unroll
    for (int nb = 0; nb < 8; ++nb) {
        float2 v0 = *(float2*)(base0 + nb * 8);
        v0.x += o[nb][0] * i0; v0.y += o[nb][1] * i0;
        *(float2*)(base0 + nb * 8) = v0;
        float2 v1 = *(float2*)(base1 + nb * 8);
        v1.x += o[nb][2] * i1; v1.y += o[nb][3] * i1;
        *(float2*)(base1 + nb * 8) = v1;
    }
}

// ---------------- K4: ps>=2 avg-pool(SAME) + 1x1 conv + BN ----------------
__global__ void k_pool(const float* __restrict__ pw, const float* __restrict__ pb,
                       const float* __restrict__ pg, const float* __restrict__ pbe,
                       const float* __restrict__ pm, const float* __restrict__ pv) {
    const int HP[4] = {64, 32, 22, 11};
    const int PS[4] = {1, 2, 3, 6};
    const int PLO[4] = {0, 0, 1, 1};
    int b = blockIdx.y;
    int lin = blockIdx.x;
    int j, r;
    if (lin < 1024)      { j = 1; r = lin; }
    else if (lin < 1508) { j = 2; r = lin - 1024; }
    else                 { j = 3; r = lin - 1508; }
    int hp = HP[j], ps = PS[j], plo = PLO[j];
    int oy = r / hp, ox = r % hp;
    __shared__ float avg[256];
    __shared__ float part[256];
    int tt = threadIdx.x;
    int ys = oy * ps - plo, xs = ox * ps - plo;
    int ye = min(ys + ps, 64), xe = min(xs + ps, 64);
    ys = max(ys, 0); xs = max(xs, 0);
    float s = 0.f;
    for (int yy = ys; yy < ye; ++yy)
        for (int xx = xs; xx < xe; ++xx)
            s += g_fused[((size_t)(b * HW) + yy * 64 + xx) * 256 + tt];
    avg[tt] = s * (1.f / (float)((ye - ys) * (xe - xs)));
    __syncthreads();
    int o = tt & 15, ck = tt >> 4;
    const float* wp = pw + j * 256 * 16 + o;
    float a = 0.f;
#pragma unroll
    for (int q = 0; q < 16; ++q) {
        int ci = ck * 16 + q;
        a += avg[ci] * wp[ci * 16];
    }
    part[ck * 16 + o] = a;
    __syncthreads();
    if (tt < 16) {
        float acc = pb[j * 16 + tt];
#pragma unroll
        for (int k2 = 0; k2 < 16; ++k2) acc += part[k2 * 16 + tt];
        int idx = j * 16 + tt;
        float sc = pg[idx] * rsqrtf(pv[idx] + 1e-3f);
        float sh = pbe[idx] - pm[idx] * sc;
        g_pool[((size_t)((j * 2 + b) * HW) + oy * hp + ox) * 16 + tt] = acc * sc + sh;
    }
}

// ---------------- K5: fused ps=1 conv + bilinear upsample + proj + BN ------
__global__ void __launch_bounds__(256) k_proj(
        const float* __restrict__ w, const float* __restrict__ pb,
        const float* __restrict__ g, const float* __restrict__ be,
        const float* __restrict__ m, const float* __restrict__ v,
        const float* __restrict__ pplw, const float* __restrict__ pplb,
        const float* __restrict__ ppg, const float* __restrict__ ppbe,
        const float* __restrict__ ppm, const float* __restrict__ ppv,
        float* __restrict__ out) {
    __shared__ float fv[16][324];
    __shared__ float ws[256 * 16];
    int tid = threadIdx.x;
    int tok0 = blockIdx.x * 16;
    int b2 = tok0 >> 12;
    int pos0 = tok0 & 4095;
    int yy = pos0 >> 6, xx0 = pos0 & 63;
#pragma unroll
    for (int i = 0; i < 4; ++i) {
        int fid = tid + i * 256;
        int px = fid >> 6, c4 = (fid & 63) * 4;
        *(float4*)&fv[px][c4] = *(const float4*)(g_fused + (size_t)(tok0 + px) * 256 + c4);
        *(float4*)&ws[fid * 4] = *(const float4*)(pplw + fid * 4);
    }
    __syncthreads();
    // ---- ps=1 pyramid level: 1x1 conv 256->16 + BN (channels 256..272) ----
    {
        int o = tid & 15, px = tid >> 4;
        float acc = pplb[o];
#pragma unroll 8
        for (int ci = 0; ci < 256; ++ci) acc += fv[px][ci] * ws[ci * 16 + o];
        float sc = ppg[o] * rsqrtf(ppv[o] + 1e-3f);
        float sh = ppbe[o] - ppm[o] * sc;
        fv[px][256 + o] = acc * sc + sh;
    }
    // ---- bilinear upsample of ps>=2 levels (channels 272..320) ----
    {
        const int HP[3] = {32, 22, 11};
#pragma unroll
        for (int k = 0; k < 3; ++k) {
            int id = tid + k * 256;
            int j = id >> 8;
            int rem = id & 255;
            int c = rem & 15, px = rem >> 4;
            int hp = HP[j];
            float scale = hp * (1.f / 64.f);
            float fy = (yy + 0.5f) * scale - 0.5f;
            float fx = (xx0 + px + 0.5f) * scale - 0.5f;
            float y0f = floorf(fy), x0f = floorf(fx);
            float ty = fy - y0f, tx = fx - x0f;
            int yA = min(max((int)y0f, 0), hp - 1);
            int yB = min(max((int)y0f + 1, 0), hp - 1);
            int xA = min(max((int)x0f, 0), hp - 1);
            int xB = min(max((int)x0f + 1, 0), hp - 1);
            const float* P = g_pool + (size_t)(((j + 1) * 2 + b2) * HW) * 16 + c;
            float v00 = P[(yA * hp + xA) * 16], v01 = P[(yA * hp + xB) * 16];
            float v10 = P[(yB * hp + xA) * 16], v11 = P[(yB * hp + xB) * 16];
            fv[px][272 + j * 16 + c] =
                (1.f - ty) * ((1.f - tx) * v00 + tx * v01)
                + ty * ((1.f - tx) * v10 + tx * v11);
        }
    }
    __syncthreads();
    // ---- proj 320->64 + BN + ReLU ----
    int co = tid & 63, tg = tid >> 6;
    int r0 = tg * 4;
    float a0 = pb[co], a1 = a0, a2 = a0, a3 = a0;
    const float* wp = w + co;
#pragma unroll 8
    for (int ci = 0; ci < 320; ++ci) {
        float wt = wp[ci * 64];
        a0 += fv[r0][ci] * wt;
        a1 += fv[r0 + 1][ci] * wt;
        a2 += fv[r0 + 2][ci] * wt;
        a3 += fv[r0 + 3][ci] * wt;
    }
    float sc = g[co] * rsqrtf(v[co] + 1e-3f);
    float sh = be[co] - m[co] * sc;
    float* op = out + (size_t)(tok0 + r0) * 64 + co;
    op[0]   = fmaxf(a0 * sc + sh, 0.f);
    op[64]  = fmaxf(a1 * sc + sh, 0.f);
    op[128] = fmaxf(a2 * sc + sh, 0.f);
    op[192] = fmaxf(a3 * sc + sh, 0.f);
}

// ---------------- launch ---------------------------------------------------
extern "C" void kernel_launch(void* const* d_in, const int* in_sizes, int n_in,
                              void* d_out, int out_size) {
    const float* x       = (const float*)d_in[0];
    const float* conv_w  = (const float*)d_in[1];
    const float* conv_b  = (const float*)d_in[2];
    const float* bn_g    = (const float*)d_in[3];
    const float* bn_b    = (const float*)d_in[4];
    const float* bn_m    = (const float*)d_in[5];
    const float* bn_v    = (const float*)d_in[6];
    const float* q_w     = (const float*)d_in[7];
    const float* q_b     = (const float*)d_in[8];
    const float* k_w     = (const float*)d_in[9];
    const float* k_b     = (const float*)d_in[10];
    const float* v_w     = (const float*)d_in[11];
    const float* v_b     = (const float*)d_in[12];
    const float* attn_g  = (const float*)d_in[13];
    const float* ppl_w   = (const float*)d_in[14];
    const float* ppl_b   = (const float*)d_in[15];
    const float* ppl_bng = (const float*)d_in[16];
    const float* ppl_bnb = (const float*)d_in[17];
    const float* ppl_bnm = (const float*)d_in[18];
    const float* ppl_bnv = (const float*)d_in[19];
    const float* proj_w  = (const float*)d_in[20];
    const float* proj_b  = (const float*)d_in[21];
    const float* pbn_g   = (const float*)d_in[22];
    const float* pbn_b   = (const float*)d_in[23];
    const float* pbn_m   = (const float*)d_in[24];
    const float* pbn_v   = (const float*)d_in[25];
    float* out = (float*)d_out;

    const int CONV_SMEM = (128 * 68 + 64 * 68 + 128) * 4;
    cudaFuncSetAttribute(k_conv, cudaFuncAttributeMaxDynamicSharedMemorySize, CONV_SMEM);

    k_conv<<<dim3(32, 8), 256, CONV_SMEM>>>(x, conv_w, conv_b, bn_g, bn_b, bn_m, bn_v);
    k_qkv<<<dim3(256, 4, 2), dim3(64, 4)>>>(q_w, q_b, k_w, k_b, v_w, v_b);
    k_attn<<<dim3(32, 4, 2), 256>>>(attn_g);
    k_pool<<<dim3(1629, 2), 256>>>(ppl_w, ppl_b, ppl_bng, ppl_bnb, ppl_bnm, ppl_bnv);
    k_proj<<<512, 256>>>(proj_w, proj_b, pbn_g, pbn_b, pbn_m, pbn_v,
                         ppl_w, ppl_b, ppl_bng, ppl_bnb, ppl_bnm, ppl_bnv, out);
}

// round 6
// speedup vs baseline: 5.9063x; 1.1456x over previous
#include <cuda_runtime.h>
#include <cuda_bf16.h>
#include <math.h>
#include <stdint.h>

#define NB 4
#define BATCH 2
#define HW 4096
#define F 64
#define LOG2E 1.4426950408889634f

// ---------------- scratch (device globals; no allocation allowed) ----------
__device__ float    g_fused[BATCH * HW * 256];        // [b][pos][256]
__device__ uint32_t g_q[BATCH * NB * HW * 8];         // tf32 bits [bb][pos][8]
__device__ uint32_t g_k[BATCH * NB * HW * 8];         // tf32 bits
// V: tile-major ldmatrix order: [bb][tile(32)][4096]:
//   off = mat*32 + row*4 + col; mat=(kpt>>2)*8+(c>>3); row=c&7; col=kpt&3
//   element = bf16x2( lo = V[2*kpt][c], hi = V[2*kpt+1][c] ), kpt in-tile pair idx
__device__ uint32_t g_vp[BATCH * NB * 32 * 4096];
__device__ float    g_pool[NB * BATCH * HW * 16];

// ---------------- helpers ---------------------------------------------------
__device__ __forceinline__ uint32_t f2tf32(float f) {
    uint32_t r; asm("cvt.rna.tf32.f32 %0, %1;" : "=r"(r) : "f"(f)); return r;
}
__device__ __forceinline__ uint32_t packbf(float hi, float lo) {
    uint32_t r; asm("cvt.rn.bf16x2.f32 %0, %1, %2;" : "=r"(r) : "f"(hi), "f"(lo)); return r;
}
__device__ __forceinline__ float ex2(float x) {
    float y; asm("ex2.approx.f32 %0, %1;" : "=f"(y) : "f"(x)); return y;
}
__device__ __forceinline__ void mma_tf32(float c[4], uint32_t a0, uint32_t a1,
                                         uint32_t a2, uint32_t a3,
                                         uint32_t b0, uint32_t b1) {
    asm volatile(
        "mma.sync.aligned.m16n8k8.row.col.f32.tf32.tf32.f32 "
        "{%0,%1,%2,%3},{%4,%5,%6,%7},{%8,%9},{%0,%1,%2,%3};"
        : "+f"(c[0]), "+f"(c[1]), "+f"(c[2]), "+f"(c[3])
        : "r"(a0), "r"(a1), "r"(a2), "r"(a3), "r"(b0), "r"(b1));
}
__device__ __forceinline__ void mma_bf16(float c[4], uint32_t a0, uint32_t a1,
                                         uint32_t a2, uint32_t a3,
                                         uint32_t b0, uint32_t b1) {
    asm volatile(
        "mma.sync.aligned.m16n8k16.row.col.f32.bf16.bf16.f32 "
        "{%0,%1,%2,%3},{%4,%5,%6,%7},{%8,%9},{%0,%1,%2,%3};"
        : "+f"(c[0]), "+f"(c[1]), "+f"(c[2]), "+f"(c[3])
        : "r"(a0), "r"(a1), "r"(a2), "r"(a3), "r"(b0), "r"(b1));
}
__device__ __forceinline__ void ldsm_x4(uint32_t& r0, uint32_t& r1,
                                        uint32_t& r2, uint32_t& r3, uint32_t addr) {
    asm volatile("ldmatrix.sync.aligned.m8n8.x4.shared.b16 {%0,%1,%2,%3}, [%4];"
        : "=r"(r0), "=r"(r1), "=r"(r2), "=r"(r3) : "r"(addr));
}
__device__ __forceinline__ void cpa16(uint32_t s, const void* g) {
    asm volatile("cp.async.cg.shared.global [%0], [%1], 16;" :: "r"(s), "l"(g));
}

// ---------------- K1: dilated conv (tf32 GEMM) + BN/ReLU + fused QKV -------
// dyn smem layout (uint32 units):
//   As/Bt 0..8704, Wt(conv W / Wv) 8704..13056, QW 13056..13600, KW 13600..14144,
//   Vt 14144..18368 (128*33), scs 18368, shs 18432, vbs 18496, qkb 18560..18576
__global__ void __launch_bounds__(256) k_conv(
        const float* __restrict__ x, const float* __restrict__ wg,
        const float* __restrict__ cb, const float* __restrict__ bg,
        const float* __restrict__ bbe, const float* __restrict__ bm,
        const float* __restrict__ bv,
        const float* __restrict__ qw, const float* __restrict__ qb,
        const float* __restrict__ kw, const float* __restrict__ kb_,
        const float* __restrict__ vw, const float* __restrict__ vb) {
    extern __shared__ uint32_t dyn[];
    uint32_t* As = dyn;
    uint32_t* Wt = dyn + 8704;
    uint32_t* QW = dyn + 13056;
    uint32_t* KW = dyn + 13600;
    uint32_t* Vt = dyn + 14144;
    float* scs = (float*)(dyn + 18368);
    float* shs = (float*)(dyn + 18432);
    float* vbs = (float*)(dyn + 18496);
    float* qkb = (float*)(dyn + 18560);

    int tid = threadIdx.x;
    int bb = blockIdx.y, b = bb >> 2, br = bb & 3;
    int d = 1 << br;
    int pix0 = blockIdx.x * 128;
    int y0 = blockIdx.x * 2;

    if (tid < 64) {
        int idx = br * 64 + tid;
        float sc = bg[idx] * rsqrtf(bv[idx] + 1e-3f);
        scs[tid] = sc;
        shs[tid] = bbe[idx] - bm[idx] * sc + cb[idx] * sc;
    }

    int w = tid >> 5, lane = tid & 31;
    int g = lane >> 2, t = lane & 3;
    int m0 = w * 16;

    float c[8][4];
#pragma unroll
    for (int nb = 0; nb < 8; ++nb) c[nb][0] = c[nb][1] = c[nb][2] = c[nb][3] = 0.f;

    int p = tid >> 1, ch = (tid & 1) * 32;
    int prow = p >> 6, pcol = p & 63;

    const uint32_t* Ar0 = As + (m0 + g) * 68 + t;
    const uint32_t* Ar1 = As + (m0 + g + 8) * 68 + t;
    const uint32_t* Wg_ = Wt + g * 68 + t;

#pragma unroll 1
    for (int tap = 0; tap < 9; ++tap) {
        int ky = tap / 3, kx = tap - ky * 3;
        __syncthreads();
        {
            int iy = y0 + prow + d * (ky - 1);
            int ix = pcol + d * (kx - 1);
            bool valid = ((unsigned)iy < 64u) & ((unsigned)ix < 64u);
            const float4* src = (const float4*)(x + (((size_t)(b * 64 + iy) * 64 + ix) * 64 + ch));
            uint4* dst = (uint4*)(As + p * 68 + ch);
#pragma unroll
            for (int i = 0; i < 8; ++i) {
                float4 v = valid ? src[i] : make_float4(0.f, 0.f, 0.f, 0.f);
                uint4 u;
                u.x = f2tf32(v.x); u.y = f2tf32(v.y);
                u.z = f2tf32(v.z); u.w = f2tf32(v.w);
                dst[i] = u;
            }
        }
        {
            const float* wtap = wg + ((size_t)(br * 9 + tap)) * 4096;
#pragma unroll
            for (int i = 0; i < 4; ++i) {
                int id = tid + i * 256;
                int ci = id >> 4, co4 = (id & 15) * 4;
                float4 v = *(const float4*)(wtap + ci * 64 + co4);
                Wt[(co4 + 0) * 68 + ci] = f2tf32(v.x);
                Wt[(co4 + 1) * 68 + ci] = f2tf32(v.y);
                Wt[(co4 + 2) * 68 + ci] = f2tf32(v.z);
                Wt[(co4 + 3) * 68 + ci] = f2tf32(v.w);
            }
        }
        __syncthreads();
#pragma unroll
        for (int k0 = 0; k0 < 64; k0 += 8) {
            uint32_t a0 = Ar0[k0], a1 = Ar1[k0];
            uint32_t a2 = Ar0[k0 + 4], a3 = Ar1[k0 + 4];
#pragma unroll
            for (int nb = 0; nb < 8; ++nb) {
                uint32_t b0 = Wg_[nb * 8 * 68 + k0];
                uint32_t b1 = Wg_[nb * 8 * 68 + k0 + 4];
                mma_tf32(c[nb], a0, a1, a2, a3, b0, b1);
            }
        }
    }
    // ---- epilogue: BN + ReLU, store g_fused ----
    float rv[8][4];
    float* f0 = g_fused + ((size_t)b * HW + pix0 + m0 + g) * 256 + br * 64;
    float* f1 = f0 + 8 * 256;
#pragma unroll
    for (int nb = 0; nb < 8; ++nb) {
        int col = nb * 8 + 2 * t;
        rv[nb][0] = fmaxf(c[nb][0] * scs[col] + shs[col], 0.f);
        rv[nb][1] = fmaxf(c[nb][1] * scs[col + 1] + shs[col + 1], 0.f);
        rv[nb][2] = fmaxf(c[nb][2] * scs[col] + shs[col], 0.f);
        rv[nb][3] = fmaxf(c[nb][3] * scs[col + 1] + shs[col + 1], 0.f);
        *(float2*)(f0 + col) = make_float2(rv[nb][0], rv[nb][1]);
        *(float2*)(f1 + col) = make_float2(rv[nb][2], rv[nb][3]);
    }
    __syncthreads();   // conv mainloop fully done; As/Wt reusable
    // ---- write Bt (tf32 of branch tile) into As region ----
#pragma unroll
    for (int nb = 0; nb < 8; ++nb) {
        int col = nb * 8 + 2 * t;
        *(uint2*)&As[(m0 + g) * 68 + col] =
            make_uint2(f2tf32(rv[nb][0]), f2tf32(rv[nb][1]));
        *(uint2*)&As[(m0 + g + 8) * 68 + col] =
            make_uint2(f2tf32(rv[nb][2]), f2tf32(rv[nb][3]));
    }
    // ---- stage Wv (tf32, [co][ci]) into Wt; Wq/Wk into QW/KW ----
#pragma unroll
    for (int i = 0; i < 4; ++i) {
        int id = tid + i * 256;
        int ci = id >> 4, co4 = (id & 15) * 4;
        float4 v = *(const float4*)(vw + br * 4096 + ci * 64 + co4);
        Wt[(co4 + 0) * 68 + ci] = f2tf32(v.x);
        Wt[(co4 + 1) * 68 + ci] = f2tf32(v.y);
        Wt[(co4 + 2) * 68 + ci] = f2tf32(v.z);
        Wt[(co4 + 3) * 68 + ci] = f2tf32(v.w);
    }
    if (tid < 128) {
        int ci = tid >> 1, d4 = (tid & 1) * 4;
        float4 v = *(const float4*)(qw + br * 512 + ci * 8 + d4);
        QW[(d4 + 0) * 68 + ci] = f2tf32(v.x * LOG2E);
        QW[(d4 + 1) * 68 + ci] = f2tf32(v.y * LOG2E);
        QW[(d4 + 2) * 68 + ci] = f2tf32(v.z * LOG2E);
        QW[(d4 + 3) * 68 + ci] = f2tf32(v.w * LOG2E);
    } else {
        int id = tid - 128;
        int ci = id >> 1, d4 = (id & 1) * 4;
        float4 v = *(const float4*)(kw + br * 512 + ci * 8 + d4);
        KW[(d4 + 0) * 68 + ci] = f2tf32(v.x);
        KW[(d4 + 1) * 68 + ci] = f2tf32(v.y);
        KW[(d4 + 2) * 68 + ci] = f2tf32(v.z);
        KW[(d4 + 3) * 68 + ci] = f2tf32(v.w);
    }
    if (tid < 64) vbs[tid] = vb[br * 64 + tid];
    if (tid >= 64 && tid < 72) qkb[tid - 64] = qb[br * 8 + tid - 64] * LOG2E;
    if (tid >= 72 && tid < 80) qkb[8 + tid - 72] = kb_[br * 8 + tid - 72];
    __syncthreads();
    // ---- V = Bt * Wv^T ----
    float vac[8][4];
#pragma unroll
    for (int nb = 0; nb < 8; ++nb) vac[nb][0] = vac[nb][1] = vac[nb][2] = vac[nb][3] = 0.f;
#pragma unroll
    for (int k0 = 0; k0 < 64; k0 += 8) {
        uint32_t a0 = Ar0[k0], a1 = Ar1[k0];
        uint32_t a2 = Ar0[k0 + 4], a3 = Ar1[k0 + 4];
#pragma unroll
        for (int nb = 0; nb < 8; ++nb)
            mma_tf32(vac[nb], a0, a1, a2, a3, Wg_[nb * 8 * 68 + k0], Wg_[nb * 8 * 68 + k0 + 4]);
    }
    // ---- Q, K (n = 8) ----
    float qa_[4] = {0.f, 0.f, 0.f, 0.f}, ka_[4] = {0.f, 0.f, 0.f, 0.f};
    const uint32_t* Qg_ = QW + g * 68 + t;
    const uint32_t* Kg_ = KW + g * 68 + t;
#pragma unroll
    for (int k0 = 0; k0 < 64; k0 += 8) {
        uint32_t a0 = Ar0[k0], a1 = Ar1[k0];
        uint32_t a2 = Ar0[k0 + 4], a3 = Ar1[k0 + 4];
        mma_tf32(qa_, a0, a1, a2, a3, Qg_[k0], Qg_[k0 + 4]);
        mma_tf32(ka_, a0, a1, a2, a3, Kg_[k0], Kg_[k0 + 4]);
    }
    {
        float b0f = qkb[2 * t], b1f = qkb[2 * t + 1];
        uint32_t* qd = g_q + ((size_t)bb * HW + pix0 + m0 + g) * 8 + 2 * t;
        *(uint2*)qd = make_uint2(f2tf32(qa_[0] + b0f), f2tf32(qa_[1] + b1f));
        *(uint2*)(qd + 64) = make_uint2(f2tf32(qa_[2] + b0f), f2tf32(qa_[3] + b1f));
        float c0f = qkb[8 + 2 * t], c1f = qkb[8 + 2 * t + 1];
        uint32_t* kd = g_k + ((size_t)bb * HW + pix0 + m0 + g) * 8 + 2 * t;
        *(uint2*)kd = make_uint2(f2tf32(ka_[0] + c0f), f2tf32(ka_[1] + c1f));
        *(uint2*)(kd + 64) = make_uint2(f2tf32(ka_[2] + c0f), f2tf32(ka_[3] + c1f));
    }
    // ---- V pack (channel pairs) into Vt[px][33] ----
#pragma unroll
    for (int nb = 0; nb < 8; ++nb) {
        int col = nb * 8 + 2 * t;
        Vt[(m0 + g) * 33 + nb * 4 + t] =
            packbf(vac[nb][1] + vbs[col + 1], vac[nb][0] + vbs[col]);
        Vt[(m0 + g + 8) * 33 + nb * 4 + t] =
            packbf(vac[nb][3] + vbs[col + 1], vac[nb][2] + vbs[col]);
    }
    __syncthreads();
    // ---- scatter Vt -> g_vp (tile-major ldmatrix order) ----
    uint32_t* vout = g_vp + ((size_t)bb * 32 + blockIdx.x) * 4096;
#pragma unroll
    for (int i = 0; i < 16; ++i) {
        int o = tid + i * 256;
        int col = o & 3, row = (o >> 2) & 7, mat = o >> 5;
        int kpt = ((mat >> 3) << 2) | col;
        int cch = ((mat & 7) << 3) | row;
        uint32_t lo = Vt[(2 * kpt) * 33 + (cch >> 1)];
        uint32_t hi = Vt[(2 * kpt + 1) * 33 + (cch >> 1)];
        vout[o] = (cch & 1) ? ((lo >> 16) | (hi & 0xFFFF0000u))
                            : ((lo & 0xFFFFu) | (hi << 16));
    }
}

// ---------------- K3: flash attention, cp.async double-buffered ------------
__global__ void __launch_bounds__(256) k_attn(const float* __restrict__ gamma) {
    __shared__ __align__(16) uint32_t Qs[1024];
    __shared__ __align__(16) uint32_t Ks[2][1024];
    __shared__ __align__(16) uint32_t Vs[2][4096];
    int tid = threadIdx.x;
    int br = blockIdx.y, b = blockIdx.z;
    int bb = b * NB + br;
    int n0 = blockIdx.x * 128;
    int w = tid >> 5, lane = tid & 31;
    int g = lane >> 2, t = lane & 3;

    const uint32_t* kgm = g_k + (size_t)bb * HW * 8;
    const uint32_t* vgm = g_vp + (size_t)bb * 32 * 4096;

    uint32_t ksa[2], vsa[2];
    ksa[0] = (uint32_t)__cvta_generic_to_shared(Ks[0]);
    ksa[1] = (uint32_t)__cvta_generic_to_shared(Ks[1]);
    vsa[0] = (uint32_t)__cvta_generic_to_shared(Vs[0]);
    vsa[1] = (uint32_t)__cvta_generic_to_shared(Vs[1]);

    // prologue: issue tiles 0,1; load Q
    cpa16(ksa[0] + tid * 16, kgm + tid * 4);
#pragma unroll
    for (int j = 0; j < 4; ++j)
        cpa16(vsa[0] + (tid + j * 256) * 16, vgm + (tid + j * 256) * 4);
    asm volatile("cp.async.commit_group;");
    ((uint4*)Qs)[tid] = ((const uint4*)(g_q + ((size_t)bb * HW + n0) * 8))[tid];
    cpa16(ksa[1] + tid * 16, kgm + 1024 + tid * 4);
#pragma unroll
    for (int j = 0; j < 4; ++j)
        cpa16(vsa[1] + (tid + j * 256) * 16, vgm + 4096 + (tid + j * 256) * 4);
    asm volatile("cp.async.commit_group;");
    asm volatile("cp.async.wait_group 1;");
    __syncthreads();

    int r0i = w * 16 + g;
    uint32_t qa0 = Qs[r0i * 8 + t];
    uint32_t qa1 = Qs[(r0i + 8) * 8 + t];
    uint32_t qa2 = Qs[r0i * 8 + t + 4];
    uint32_t qa3 = Qs[(r0i + 8) * 8 + t + 4];

    int midx = lane >> 3;
    int lane_const = (midx & 1) * 8 + (midx >> 1);
    uint32_t lboff = (uint32_t)((lane_const * 32 + (lane & 7) * 4) * 4);

    float o[8][4];
#pragma unroll
    for (int nb = 0; nb < 8; ++nb) { o[nb][0] = o[nb][1] = o[nb][2] = o[nb][3] = 0.f; }
    float m0 = -1e30f, m1 = -1e30f, Z0 = 0.f, Z1 = 0.f;

#pragma unroll 1
    for (int it = 0; it < 32; ++it) {
        int cur = it & 1;
        const uint32_t* Kc = Ks[cur];
        uint32_t lb = vsa[cur] + lboff;

        float s[16][4];
#pragma unroll
        for (int nb = 0; nb < 16; ++nb) {
            uint32_t b0 = Kc[(nb * 8 + g) * 8 + t];
            uint32_t b1 = Kc[(nb * 8 + g) * 8 + t + 4];
            s[nb][0] = s[nb][1] = s[nb][2] = s[nb][3] = 0.f;
            mma_tf32(s[nb], qa0, qa1, qa2, qa3, b0, b1);
        }
        float r0 = -1e30f, r1 = -1e30f;
#pragma unroll
        for (int nb = 0; nb < 16; ++nb) {
            r0 = fmaxf(r0, fmaxf(s[nb][0], s[nb][1]));
            r1 = fmaxf(r1, fmaxf(s[nb][2], s[nb][3]));
        }
        r0 = fmaxf(r0, __shfl_xor_sync(0xffffffffu, r0, 1));
        r0 = fmaxf(r0, __shfl_xor_sync(0xffffffffu, r0, 2));
        r1 = fmaxf(r1, __shfl_xor_sync(0xffffffffu, r1, 1));
        r1 = fmaxf(r1, __shfl_xor_sync(0xffffffffu, r1, 2));
        float m0n = fmaxf(m0, r0), m1n = fmaxf(m1, r1);
        float sc0 = ex2(m0 - m0n), sc1 = ex2(m1 - m1n);
        m0 = m0n; m1 = m1n;
        Z0 *= sc0; Z1 *= sc1;
#pragma unroll
        for (int nb = 0; nb < 8; ++nb) {
            o[nb][0] *= sc0; o[nb][1] *= sc0; o[nb][2] *= sc1; o[nb][3] *= sc1;
        }
        uint32_t pa[16][2];
#pragma unroll
        for (int j = 0; j < 16; ++j) {
            float p0 = ex2(s[j][0] - m0), p1 = ex2(s[j][1] - m0);
            float p2 = ex2(s[j][2] - m1), p3 = ex2(s[j][3] - m1);
            Z0 += p0 + p1; Z1 += p2 + p3;
            pa[j][0] = packbf(p1, p0);
            pa[j][1] = packbf(p3, p2);
        }
#pragma unroll
        for (int ks = 0; ks < 8; ++ks) {
#pragma unroll
            for (int nbp = 0; nbp < 4; ++nbp) {
                uint32_t b00, b10, b01, b11;
                ldsm_x4(b00, b10, b01, b11, lb + (uint32_t)((16 * ks + 2 * nbp) * 128));
                mma_bf16(o[2 * nbp], pa[2 * ks][0], pa[2 * ks][1],
                         pa[2 * ks + 1][0], pa[2 * ks + 1][1], b00, b10);
                mma_bf16(o[2 * nbp + 1], pa[2 * ks][0], pa[2 * ks][1],
                         pa[2 * ks + 1][0], pa[2 * ks + 1][1], b01, b11);
            }
        }
        __syncthreads();   // done reading buf cur
        if (it + 2 < 32) {
            int t2 = it + 2;
            cpa16(ksa[cur] + tid * 16, kgm + (size_t)t2 * 1024 + tid * 4);
#pragma unroll
            for (int j = 0; j < 4; ++j)
                cpa16(vsa[cur] + (tid + j * 256) * 16,
                      vgm + (size_t)t2 * 4096 + (tid + j * 256) * 4);
            asm volatile("cp.async.commit_group;");
            asm volatile("cp.async.wait_group 1;");
            __syncthreads();
        } else if (it + 1 < 32) {
            asm volatile("cp.async.wait_group 0;");
            __syncthreads();
        }
    }
    Z0 += __shfl_xor_sync(0xffffffffu, Z0, 1);
    Z0 += __shfl_xor_sync(0xffffffffu, Z0, 2);
    Z1 += __shfl_xor_sync(0xffffffffu, Z1, 1);
    Z1 += __shfl_xor_sync(0xffffffffu, Z1, 2);
    float ga = gamma[br];
    float i0 = ga / Z0, i1 = ga / Z1;
    float* base0 = g_fused + ((size_t)b * HW + n0 + w * 16 + g) * 256 + br * 64 + 2 * t;
    float* base1 = base0 + 8 * 256;
#pragma unroll
    for (int nb = 0; nb < 8; ++nb) {
        float2 v0 = *(float2*)(base0 + nb * 8);
        v0.x += o[nb][0] * i0; v0.y += o[nb][1] * i0;
        *(float2*)(base0 + nb * 8) = v0;
        float2 v1 = *(float2*)(base1 + nb * 8);
        v1.x += o[nb][2] * i1; v1.y += o[nb][3] * i1;
        *(float2*)(base1 + nb * 8) = v1;
    }
}

// ---------------- K4: ps>=2 avg-pool(SAME) + 1x1 conv + BN ----------------
__global__ void k_pool(const float* __restrict__ pw, const float* __restrict__ pb,
                       const float* __restrict__ pg, const float* __restrict__ pbe,
                       const float* __restrict__ pm, const float* __restrict__ pv) {
    const int HP[4] = {64, 32, 22, 11};
    const int PS[4] = {1, 2, 3, 6};
    const int PLO[4] = {0, 0, 1, 1};
    int b = blockIdx.y;
    int lin = blockIdx.x;
    int j, r;
    if (lin < 1024)      { j = 1; r = lin; }
    else if (lin < 1508) { j = 2; r = lin - 1024; }
    else                 { j = 3; r = lin - 1508; }
    int hp = HP[j], ps = PS[j], plo = PLO[j];
    int oy = r / hp, ox = r % hp;
    __shared__ float avg[256];
    __shared__ float part[256];
    int tt = threadIdx.x;
    int ys = oy * ps - plo, xs = ox * ps - plo;
    int ye = min(ys + ps, 64), xe = min(xs + ps, 64);
    ys = max(ys, 0); xs = max(xs, 0);
    float s = 0.f;
    for (int yy = ys; yy < ye; ++yy)
        for (int xx = xs; xx < xe; ++xx)
            s += g_fused[((size_t)(b * HW) + yy * 64 + xx) * 256 + tt];
    avg[tt] = s * (1.f / (float)((ye - ys) * (xe - xs)));
    __syncthreads();
    int o = tt & 15, ck = tt >> 4;
    const float* wp = pw + j * 256 * 16 + o;
    float a = 0.f;
#pragma unroll
    for (int q = 0; q < 16; ++q) {
        int ci = ck * 16 + q;
        a += avg[ci] * wp[ci * 16];
    }
    part[ck * 16 + o] = a;
    __syncthreads();
    if (tt < 16) {
        float acc = pb[j * 16 + tt];
#pragma unroll
        for (int k2 = 0; k2 < 16; ++k2) acc += part[k2 * 16 + tt];
        int idx = j * 16 + tt;
        float sc = pg[idx] * rsqrtf(pv[idx] + 1e-3f);
        float sh = pbe[idx] - pm[idx] * sc;
        g_pool[((size_t)((j * 2 + b) * HW) + oy * hp + ox) * 16 + tt] = acc * sc + sh;
    }
}

// ---------------- K5: fused ps=1 conv + bilinear upsample + proj + BN ------
__global__ void __launch_bounds__(256) k_proj(
        const float* __restrict__ w, const float* __restrict__ pb,
        const float* __restrict__ g, const float* __restrict__ be,
        const float* __restrict__ m, const float* __restrict__ v,
        const float* __restrict__ pplw, const float* __restrict__ pplb,
        const float* __restrict__ ppg, const float* __restrict__ ppbe,
        const float* __restrict__ ppm, const float* __restrict__ ppv,
        float* __restrict__ out) {
    __shared__ float fv[16][324];
    __shared__ float ws[256 * 16];
    int tid = threadIdx.x;
    int tok0 = blockIdx.x * 16;
    int b2 = tok0 >> 12;
    int pos0 = tok0 & 4095;
    int yy = pos0 >> 6, xx0 = pos0 & 63;
#pragma unroll
    for (int i = 0; i < 4; ++i) {
        int fid = tid + i * 256;
        int px = fid >> 6, c4 = (fid & 63) * 4;
        *(float4*)&fv[px][c4] = *(const float4*)(g_fused + (size_t)(tok0 + px) * 256 + c4);
        *(float4*)&ws[fid * 4] = *(const float4*)(pplw + fid * 4);
    }
    __syncthreads();
    {
        int o = tid & 15, px = tid >> 4;
        float acc = pplb[o];
#pragma unroll 8
        for (int ci = 0; ci < 256; ++ci) acc += fv[px][ci] * ws[ci * 16 + o];
        float sc = ppg[o] * rsqrtf(ppv[o] + 1e-3f);
        float sh = ppbe[o] - ppm[o] * sc;
        fv[px][256 + o] = acc * sc + sh;
    }
    {
        const int HP[3] = {32, 22, 11};
#pragma unroll
        for (int k = 0; k < 3; ++k) {
            int id = tid + k * 256;
            int j = id >> 8;
            int rem = id & 255;
            int c = rem & 15, px = rem >> 4;
            int hp = HP[j];
            float scale = hp * (1.f / 64.f);
            float fy = (yy + 0.5f) * scale - 0.5f;
            float fx = (xx0 + px + 0.5f) * scale - 0.5f;
            float y0f = floorf(fy), x0f = floorf(fx);
            float ty = fy - y0f, tx = fx - x0f;
            int yA = min(max((int)y0f, 0), hp - 1);
            int yB = min(max((int)y0f + 1, 0), hp - 1);
            int xA = min(max((int)x0f, 0), hp - 1);
            int xB = min(max((int)x0f + 1, 0), hp - 1);
            const float* P = g_pool + (size_t)(((j + 1) * 2 + b2) * HW) * 16 + c;
            float v00 = P[(yA * hp + xA) * 16], v01 = P[(yA * hp + xB) * 16];
            float v10 = P[(yB * hp + xA) * 16], v11 = P[(yB * hp + xB) * 16];
            fv[px][272 + j * 16 + c] =
                (1.f - ty) * ((1.f - tx) * v00 + tx * v01)
                + ty * ((1.f - tx) * v10 + tx * v11);
        }
    }
    __syncthreads();
    int co = tid & 63, tg = tid >> 6;
    int r0 = tg * 4;
    float a0 = pb[co], a1 = a0, a2 = a0, a3 = a0;
    const float* wp = w + co;
#pragma unroll 8
    for (int ci = 0; ci < 320; ++ci) {
        float wt = wp[ci * 64];
        a0 += fv[r0][ci] * wt;
        a1 += fv[r0 + 1][ci] * wt;
        a2 += fv[r0 + 2][ci] * wt;
        a3 += fv[r0 + 3][ci] * wt;
    }
    float sc = g[co] * rsqrtf(v[co] + 1e-3f);
    float sh = be[co] - m[co] * sc;
    float* op = out + (size_t)(tok0 + r0) * 64 + co;
    op[0]   = fmaxf(a0 * sc + sh, 0.f);
    op[64]  = fmaxf(a1 * sc + sh, 0.f);
    op[128] = fmaxf(a2 * sc + sh, 0.f);
    op[192] = fmaxf(a3 * sc + sh, 0.f);
}

// ---------------- launch ---------------------------------------------------
extern "C" void kernel_launch(void* const* d_in, const int* in_sizes, int n_in,
                              void* d_out, int out_size) {
    const float* x       = (const float*)d_in[0];
    const float* conv_w  = (const float*)d_in[1];
    const float* conv_b  = (const float*)d_in[2];
    const float* bn_g    = (const float*)d_in[3];
    const float* bn_b    = (const float*)d_in[4];
    const float* bn_m    = (const float*)d_in[5];
    const float* bn_v    = (const float*)d_in[6];
    const float* q_w     = (const float*)d_in[7];
    const float* q_b     = (const float*)d_in[8];
    const float* k_w     = (const float*)d_in[9];
    const float* k_b     = (const float*)d_in[10];
    const float* v_w     = (const float*)d_in[11];
    const float* v_b     = (const float*)d_in[12];
    const float* attn_g  = (const float*)d_in[13];
    const float* ppl_w   = (const float*)d_in[14];
    const float* ppl_b   = (const float*)d_in[15];
    const float* ppl_bng = (const float*)d_in[16];
    const float* ppl_bnb = (const float*)d_in[17];
    const float* ppl_bnm = (const float*)d_in[18];
    const float* ppl_bnv = (const float*)d_in[19];
    const float* proj_w  = (const float*)d_in[20];
    const float* proj_b  = (const float*)d_in[21];
    const float* pbn_g   = (const float*)d_in[22];
    const float* pbn_b   = (const float*)d_in[23];
    const float* pbn_m   = (const float*)d_in[24];
    const float* pbn_v   = (const float*)d_in[25];
    float* out = (float*)d_out;

    const int CONV_SMEM = 18576 * 4;  // 74,304 B
    cudaFuncSetAttribute(k_conv, cudaFuncAttributeMaxDynamicSharedMemorySize, CONV_SMEM);

    k_conv<<<dim3(32, 8), 256, CONV_SMEM>>>(x, conv_w, conv_b, bn_g, bn_b, bn_m, bn_v,
                                            q_w, q_b, k_w, k_b, v_w, v_b);
    k_attn<<<dim3(32, 4, 2), 256>>>(attn_g);
    k_pool<<<dim3(1629, 2), 256>>>(ppl_w, ppl_b, ppl_bng, ppl_bnb, ppl_bnm, ppl_bnv);
    k_proj<<<512, 256>>>(proj_w, proj_b, pbn_g, pbn_b, pbn_m, pbn_v,
                         ppl_w, ppl_b, ppl_bng, ppl_bnb, ppl_bnm, ppl_bnv, out);
}

// round 7
// speedup vs baseline: 7.0048x; 1.1860x over previous
#include <cuda_runtime.h>
#include <cuda_bf16.h>
#include <math.h>
#include <stdint.h>

#define NB 4
#define BATCH 2
#define HW 4096
#define F 64
#define LOG2E 1.4426950408889634f

// ---------------- scratch (device globals; no allocation allowed) ----------
__device__ float    g_fused[BATCH * HW * 256];        // [b][pos][256]
__device__ uint32_t g_q[BATCH * NB * HW * 8];         // tf32 bits [bb][pos][8]
__device__ uint32_t g_k[BATCH * NB * HW * 8];         // tf32 bits
__device__ uint32_t g_vp[BATCH * NB * 32 * 4096];     // tile-major ldmatrix order
__device__ float    g_pool[NB * BATCH * HW * 16];

// ---------------- helpers ---------------------------------------------------
__device__ __forceinline__ uint32_t f2tf32(float f) {
    uint32_t r; asm("cvt.rna.tf32.f32 %0, %1;" : "=r"(r) : "f"(f)); return r;
}
__device__ __forceinline__ uint32_t packbf(float hi, float lo) {
    uint32_t r; asm("cvt.rn.bf16x2.f32 %0, %1, %2;" : "=r"(r) : "f"(hi), "f"(lo)); return r;
}
__device__ __forceinline__ float ex2(float x) {
    float y; asm("ex2.approx.f32 %0, %1;" : "=f"(y) : "f"(x)); return y;
}
__device__ __forceinline__ void mma_tf32(float c[4], uint32_t a0, uint32_t a1,
                                         uint32_t a2, uint32_t a3,
                                         uint32_t b0, uint32_t b1) {
    asm volatile(
        "mma.sync.aligned.m16n8k8.row.col.f32.tf32.tf32.f32 "
        "{%0,%1,%2,%3},{%4,%5,%6,%7},{%8,%9},{%0,%1,%2,%3};"
        : "+f"(c[0]), "+f"(c[1]), "+f"(c[2]), "+f"(c[3])
        : "r"(a0), "r"(a1), "r"(a2), "r"(a3), "r"(b0), "r"(b1));
}
__device__ __forceinline__ void mma_bf16(float c[4], uint32_t a0, uint32_t a1,
                                         uint32_t a2, uint32_t a3,
                                         uint32_t b0, uint32_t b1) {
    asm volatile(
        "mma.sync.aligned.m16n8k16.row.col.f32.bf16.bf16.f32 "
        "{%0,%1,%2,%3},{%4,%5,%6,%7},{%8,%9},{%0,%1,%2,%3};"
        : "+f"(c[0]), "+f"(c[1]), "+f"(c[2]), "+f"(c[3])
        : "r"(a0), "r"(a1), "r"(a2), "r"(a3), "r"(b0), "r"(b1));
}
__device__ __forceinline__ void ldsm_x4(uint32_t& r0, uint32_t& r1,
                                        uint32_t& r2, uint32_t& r3, uint32_t addr) {
    asm volatile("ldmatrix.sync.aligned.m8n8.x4.shared.b16 {%0,%1,%2,%3}, [%4];"
        : "=r"(r0), "=r"(r1), "=r"(r2), "=r"(r3) : "r"(addr));
}
__device__ __forceinline__ void cpa16(uint32_t s, const void* g) {
    asm volatile("cp.async.cg.shared.global [%0], [%1], 16;" :: "r"(s), "l"(g));
}
__device__ __forceinline__ void cpa16z(uint32_t s, const void* g, int sz) {
    asm volatile("cp.async.cg.shared.global [%0], [%1], 16, %2;" :: "r"(s), "l"(g), "r"(sz));
}

// ---------------- K1: dilated conv (tf32 GEMM) + BN/ReLU + fused QKV -------
__global__ void __launch_bounds__(256) k_conv(
        const float* __restrict__ x, const float* __restrict__ wg,
        const float* __restrict__ cb, const float* __restrict__ bg,
        const float* __restrict__ bbe, const float* __restrict__ bm,
        const float* __restrict__ bv,
        const float* __restrict__ qw, const float* __restrict__ qb,
        const float* __restrict__ kw, const float* __restrict__ kb_,
        const float* __restrict__ vw, const float* __restrict__ vb) {
    extern __shared__ uint32_t dyn[];
    uint32_t* As = dyn;                   // 128*68
    uint32_t* Wt = dyn + 8704;            // 64*68
    uint32_t* QW = dyn + 13056;
    uint32_t* KW = dyn + 13600;
    uint32_t* Vt = dyn + 14144;           // 128*33
    float* scs = (float*)(dyn + 18368);
    float* shs = (float*)(dyn + 18432);
    float* vbs = (float*)(dyn + 18496);
    float* qkb = (float*)(dyn + 18560);

    int tid = threadIdx.x;
    int bb = blockIdx.y, b = bb >> 2, br = bb & 3;
    int d = 1 << br;
    int pix0 = blockIdx.x * 128;
    int y0 = blockIdx.x * 2;

    if (tid < 64) {
        int idx = br * 64 + tid;
        float sc = bg[idx] * rsqrtf(bv[idx] + 1e-3f);
        scs[tid] = sc;
        shs[tid] = bbe[idx] - bm[idx] * sc + cb[idx] * sc;
    }

    int w = tid >> 5, lane = tid & 31;
    int g = lane >> 2, t = lane & 3;
    int m0 = w * 16;

    float c[8][4];
#pragma unroll
    for (int nb = 0; nb < 8; ++nb) c[nb][0] = c[nb][1] = c[nb][2] = c[nb][3] = 0.f;

    int p = tid >> 1, ch = (tid & 1) * 32;
    int prow = p >> 6, pcol = p & 63;

    uint32_t as_sh = (uint32_t)__cvta_generic_to_shared(As);
    uint32_t a_dst = as_sh + (uint32_t)((p * 68 + ch) * 4);

    const uint32_t* Ar0 = As + (m0 + g) * 68 + t;
    const uint32_t* Ar1 = As + (m0 + g + 8) * 68 + t;
    const uint32_t* Wg_ = Wt + g * 68 + t;

#pragma unroll 1
    for (int tap = 0; tap < 9; ++tap) {
        int ky = tap / 3, kx = tap - ky * 3;
        __syncthreads();
        // ---- A tile via cp.async (raw fp32 bits; zfill out-of-bounds) ----
        {
            int iy = y0 + prow + d * (ky - 1);
            int ix = pcol + d * (kx - 1);
            int valid = (((unsigned)iy < 64u) & ((unsigned)ix < 64u)) ? 16 : 0;
            int iyc = min(max(iy, 0), 63), ixc = min(max(ix, 0), 63);
            const float* src = x + (((size_t)(b * 64 + iyc) * 64 + ixc) * 64 + ch);
#pragma unroll
            for (int i = 0; i < 8; ++i)
                cpa16z(a_dst + i * 16, src + i * 4, valid);
        }
        // ---- W tap (overlaps with A copy), cvt.rna ----
        {
            const float* wtap = wg + ((size_t)(br * 9 + tap)) * 4096;
#pragma unroll
            for (int i = 0; i < 4; ++i) {
                int id = tid + i * 256;
                int ci = id >> 4, co4 = (id & 15) * 4;
                float4 v = *(const float4*)(wtap + ci * 64 + co4);
                Wt[(co4 + 0) * 68 + ci] = f2tf32(v.x);
                Wt[(co4 + 1) * 68 + ci] = f2tf32(v.y);
                Wt[(co4 + 2) * 68 + ci] = f2tf32(v.z);
                Wt[(co4 + 3) * 68 + ci] = f2tf32(v.w);
            }
        }
        asm volatile("cp.async.commit_group;");
        asm volatile("cp.async.wait_group 0;");
        __syncthreads();
#pragma unroll
        for (int k0 = 0; k0 < 64; k0 += 8) {
            uint32_t a0 = Ar0[k0], a1 = Ar1[k0];
            uint32_t a2 = Ar0[k0 + 4], a3 = Ar1[k0 + 4];
#pragma unroll
            for (int nb = 0; nb < 8; ++nb) {
                uint32_t b0 = Wg_[nb * 8 * 68 + k0];
                uint32_t b1 = Wg_[nb * 8 * 68 + k0 + 4];
                mma_tf32(c[nb], a0, a1, a2, a3, b0, b1);
            }
        }
    }
    // ---- epilogue: BN + ReLU, store g_fused ----
    float rv[8][4];
    float* f0 = g_fused + ((size_t)b * HW + pix0 + m0 + g) * 256 + br * 64;
    float* f1 = f0 + 8 * 256;
#pragma unroll
    for (int nb = 0; nb < 8; ++nb) {
        int col = nb * 8 + 2 * t;
        rv[nb][0] = fmaxf(c[nb][0] * scs[col] + shs[col], 0.f);
        rv[nb][1] = fmaxf(c[nb][1] * scs[col + 1] + shs[col + 1], 0.f);
        rv[nb][2] = fmaxf(c[nb][2] * scs[col] + shs[col], 0.f);
        rv[nb][3] = fmaxf(c[nb][3] * scs[col + 1] + shs[col + 1], 0.f);
        *(float2*)(f0 + col) = make_float2(rv[nb][0], rv[nb][1]);
        *(float2*)(f1 + col) = make_float2(rv[nb][2], rv[nb][3]);
    }
    __syncthreads();
    // ---- write Bt (tf32 of branch tile) into As region ----
#pragma unroll
    for (int nb = 0; nb < 8; ++nb) {
        int col = nb * 8 + 2 * t;
        *(uint2*)&As[(m0 + g) * 68 + col] =
            make_uint2(f2tf32(rv[nb][0]), f2tf32(rv[nb][1]));
        *(uint2*)&As[(m0 + g + 8) * 68 + col] =
            make_uint2(f2tf32(rv[nb][2]), f2tf32(rv[nb][3]));
    }
    // ---- stage Wv/Wq/Wk ----
#pragma unroll
    for (int i = 0; i < 4; ++i) {
        int id = tid + i * 256;
        int ci = id >> 4, co4 = (id & 15) * 4;
        float4 v = *(const float4*)(vw + br * 4096 + ci * 64 + co4);
        Wt[(co4 + 0) * 68 + ci] = f2tf32(v.x);
        Wt[(co4 + 1) * 68 + ci] = f2tf32(v.y);
        Wt[(co4 + 2) * 68 + ci] = f2tf32(v.z);
        Wt[(co4 + 3) * 68 + ci] = f2tf32(v.w);
    }
    if (tid < 128) {
        int ci = tid >> 1, d4 = (tid & 1) * 4;
        float4 v = *(const float4*)(qw + br * 512 + ci * 8 + d4);
        QW[(d4 + 0) * 68 + ci] = f2tf32(v.x * LOG2E);
        QW[(d4 + 1) * 68 + ci] = f2tf32(v.y * LOG2E);
        QW[(d4 + 2) * 68 + ci] = f2tf32(v.z * LOG2E);
        QW[(d4 + 3) * 68 + ci] = f2tf32(v.w * LOG2E);
    } else {
        int id = tid - 128;
        int ci = id >> 1, d4 = (id & 1) * 4;
        float4 v = *(const float4*)(kw + br * 512 + ci * 8 + d4);
        KW[(d4 + 0) * 68 + ci] = f2tf32(v.x);
        KW[(d4 + 1) * 68 + ci] = f2tf32(v.y);
        KW[(d4 + 2) * 68 + ci] = f2tf32(v.z);
        KW[(d4 + 3) * 68 + ci] = f2tf32(v.w);
    }
    if (tid < 64) vbs[tid] = vb[br * 64 + tid];
    if (tid >= 64 && tid < 72) qkb[tid - 64] = qb[br * 8 + tid - 64] * LOG2E;
    if (tid >= 72 && tid < 80) qkb[8 + tid - 72] = kb_[br * 8 + tid - 72];
    __syncthreads();
    // ---- V = Bt * Wv^T ----
    float vac[8][4];
#pragma unroll
    for (int nb = 0; nb < 8; ++nb) vac[nb][0] = vac[nb][1] = vac[nb][2] = vac[nb][3] = 0.f;
#pragma unroll
    for (int k0 = 0; k0 < 64; k0 += 8) {
        uint32_t a0 = Ar0[k0], a1 = Ar1[k0];
        uint32_t a2 = Ar0[k0 + 4], a3 = Ar1[k0 + 4];
#pragma unroll
        for (int nb = 0; nb < 8; ++nb)
            mma_tf32(vac[nb], a0, a1, a2, a3, Wg_[nb * 8 * 68 + k0], Wg_[nb * 8 * 68 + k0 + 4]);
    }
    // ---- Q, K ----
    float qa_[4] = {0.f, 0.f, 0.f, 0.f}, ka_[4] = {0.f, 0.f, 0.f, 0.f};
    const uint32_t* Qg_ = QW + g * 68 + t;
    const uint32_t* Kg_ = KW + g * 68 + t;
#pragma unroll
    for (int k0 = 0; k0 < 64; k0 += 8) {
        uint32_t a0 = Ar0[k0], a1 = Ar1[k0];
        uint32_t a2 = Ar0[k0 + 4], a3 = Ar1[k0 + 4];
        mma_tf32(qa_, a0, a1, a2, a3, Qg_[k0], Qg_[k0 + 4]);
        mma_tf32(ka_, a0, a1, a2, a3, Kg_[k0], Kg_[k0 + 4]);
    }
    {
        float b0f = qkb[2 * t], b1f = qkb[2 * t + 1];
        uint32_t* qd = g_q + ((size_t)bb * HW + pix0 + m0 + g) * 8 + 2 * t;
        *(uint2*)qd = make_uint2(f2tf32(qa_[0] + b0f), f2tf32(qa_[1] + b1f));
        *(uint2*)(qd + 64) = make_uint2(f2tf32(qa_[2] + b0f), f2tf32(qa_[3] + b1f));
        float c0f = qkb[8 + 2 * t], c1f = qkb[8 + 2 * t + 1];
        uint32_t* kd = g_k + ((size_t)bb * HW + pix0 + m0 + g) * 8 + 2 * t;
        *(uint2*)kd = make_uint2(f2tf32(ka_[0] + c0f), f2tf32(ka_[1] + c1f));
        *(uint2*)(kd + 64) = make_uint2(f2tf32(ka_[2] + c0f), f2tf32(ka_[3] + c1f));
    }
    // ---- V pack into Vt[px][33] ----
#pragma unroll
    for (int nb = 0; nb < 8; ++nb) {
        int col = nb * 8 + 2 * t;
        Vt[(m0 + g) * 33 + nb * 4 + t] =
            packbf(vac[nb][1] + vbs[col + 1], vac[nb][0] + vbs[col]);
        Vt[(m0 + g + 8) * 33 + nb * 4 + t] =
            packbf(vac[nb][3] + vbs[col + 1], vac[nb][2] + vbs[col]);
    }
    __syncthreads();
    // ---- scatter Vt -> g_vp (tile-major ldmatrix order) ----
    uint32_t* vout = g_vp + ((size_t)bb * 32 + blockIdx.x) * 4096;
#pragma unroll
    for (int i = 0; i < 16; ++i) {
        int o = tid + i * 256;
        int col = o & 3, row = (o >> 2) & 7, mat = o >> 5;
        int kpt = ((mat >> 3) << 2) | col;
        int cch = ((mat & 7) << 3) | row;
        uint32_t lo = Vt[(2 * kpt) * 33 + (cch >> 1)];
        uint32_t hi = Vt[(2 * kpt + 1) * 33 + (cch >> 1)];
        vout[o] = (cch & 1) ? ((lo >> 16) | (hi & 0xFFFF0000u))
                            : ((lo & 0xFFFFu) | (hi << 16));
    }
}

// ---------------- K3: flash attention (no-max softmax), cp.async pipelined -
__global__ void __launch_bounds__(256) k_attn(const float* __restrict__ gamma) {
    __shared__ __align__(16) uint32_t Qs[1024];
    __shared__ __align__(16) uint32_t Ks[2][1024];
    __shared__ __align__(16) uint32_t Vs[2][4096];
    int tid = threadIdx.x;
    int br = blockIdx.y, b = blockIdx.z;
    int bb = b * NB + br;
    int n0 = blockIdx.x * 128;
    int w = tid >> 5, lane = tid & 31;
    int g = lane >> 2, t = lane & 3;

    const uint32_t* kgm = g_k + (size_t)bb * HW * 8;
    const uint32_t* vgm = g_vp + (size_t)bb * 32 * 4096;

    uint32_t ksa[2], vsa[2];
    ksa[0] = (uint32_t)__cvta_generic_to_shared(Ks[0]);
    ksa[1] = (uint32_t)__cvta_generic_to_shared(Ks[1]);
    vsa[0] = (uint32_t)__cvta_generic_to_shared(Vs[0]);
    vsa[1] = (uint32_t)__cvta_generic_to_shared(Vs[1]);

    cpa16(ksa[0] + tid * 16, kgm + tid * 4);
#pragma unroll
    for (int j = 0; j < 4; ++j)
        cpa16(vsa[0] + (tid + j * 256) * 16, vgm + (tid + j * 256) * 4);
    asm volatile("cp.async.commit_group;");
    ((uint4*)Qs)[tid] = ((const uint4*)(g_q + ((size_t)bb * HW + n0) * 8))[tid];
    cpa16(ksa[1] + tid * 16, kgm + 1024 + tid * 4);
#pragma unroll
    for (int j = 0; j < 4; ++j)
        cpa16(vsa[1] + (tid + j * 256) * 16, vgm + 4096 + (tid + j * 256) * 4);
    asm volatile("cp.async.commit_group;");
    asm volatile("cp.async.wait_group 1;");
    __syncthreads();

    int r0i = w * 16 + g;
    uint32_t qa0 = Qs[r0i * 8 + t];
    uint32_t qa1 = Qs[(r0i + 8) * 8 + t];
    uint32_t qa2 = Qs[r0i * 8 + t + 4];
    uint32_t qa3 = Qs[(r0i + 8) * 8 + t + 4];

    int midx = lane >> 3;
    int lane_const = (midx & 1) * 8 + (midx >> 1);
    uint32_t lboff = (uint32_t)((lane_const * 32 + (lane & 7) * 4) * 4);

    float o[8][4];
#pragma unroll
    for (int nb = 0; nb < 8; ++nb) { o[nb][0] = o[nb][1] = o[nb][2] = o[nb][3] = 0.f; }
    float Z0 = 0.f, Z1 = 0.f;

#pragma unroll 1
    for (int it = 0; it < 32; ++it) {
        int cur = it & 1;
        const uint32_t* Kc = Ks[cur];
        uint32_t lb = vsa[cur] + lboff;

        float s[16][4];
#pragma unroll
        for (int nb = 0; nb < 16; ++nb) {
            uint32_t b0 = Kc[(nb * 8 + g) * 8 + t];
            uint32_t b1 = Kc[(nb * 8 + g) * 8 + t + 4];
            s[nb][0] = s[nb][1] = s[nb][2] = s[nb][3] = 0.f;
            mma_tf32(s[nb], qa0, qa1, qa2, qa3, b0, b1);
        }
        // softmax without max shift (scores structurally bounded)
        uint32_t pa[16][2];
#pragma unroll
        for (int j = 0; j < 16; ++j) {
            float p0 = ex2(s[j][0]), p1 = ex2(s[j][1]);
            float p2 = ex2(s[j][2]), p3 = ex2(s[j][3]);
            Z0 += p0 + p1; Z1 += p2 + p3;
            pa[j][0] = packbf(p1, p0);
            pa[j][1] = packbf(p3, p2);
        }
#pragma unroll
        for (int ks = 0; ks < 8; ++ks) {
#pragma unroll
            for (int nbp = 0; nbp < 4; ++nbp) {
                uint32_t b00, b10, b01, b11;
                ldsm_x4(b00, b10, b01, b11, lb + (uint32_t)((16 * ks + 2 * nbp) * 128));
                mma_bf16(o[2 * nbp], pa[2 * ks][0], pa[2 * ks][1],
                         pa[2 * ks + 1][0], pa[2 * ks + 1][1], b00, b10);
                mma_bf16(o[2 * nbp + 1], pa[2 * ks][0], pa[2 * ks][1],
                         pa[2 * ks + 1][0], pa[2 * ks + 1][1], b01, b11);
            }
        }
        __syncthreads();
        if (it + 2 < 32) {
            int t2 = it + 2;
            cpa16(ksa[cur] + tid * 16, kgm + (size_t)t2 * 1024 + tid * 4);
#pragma unroll
            for (int j = 0; j < 4; ++j)
                cpa16(vsa[cur] + (tid + j * 256) * 16,
                      vgm + (size_t)t2 * 4096 + (tid + j * 256) * 4);
            asm volatile("cp.async.commit_group;");
            asm volatile("cp.async.wait_group 1;");
            __syncthreads();
        } else if (it + 1 < 32) {
            asm volatile("cp.async.wait_group 0;");
            __syncthreads();
        }
    }
    Z0 += __shfl_xor_sync(0xffffffffu, Z0, 1);
    Z0 += __shfl_xor_sync(0xffffffffu, Z0, 2);
    Z1 += __shfl_xor_sync(0xffffffffu, Z1, 1);
    Z1 += __shfl_xor_sync(0xffffffffu, Z1, 2);
    float ga = gamma[br];
    float i0 = ga / Z0, i1 = ga / Z1;
    float* base0 = g_fused + ((size_t)b * HW + n0 + w * 16 + g) * 256 + br * 64 + 2 * t;
    float* base1 = base0 + 8 * 256;
#pragma unroll
    for (int nb = 0; nb < 8; ++nb) {
        float2 v0 = *(float2*)(base0 + nb * 8);
        v0.x += o[nb][0] * i0; v0.y += o[nb][1] * i0;
        *(float2*)(base0 + nb * 8) = v0;
        float2 v1 = *(float2*)(base1 + nb * 8);
        v1.x += o[nb][2] * i1; v1.y += o[nb][3] * i1;
        *(float2*)(base1 + nb * 8) = v1;
    }
}

// ---------------- K4: ps>=2 avg-pool(SAME) + 1x1 conv + BN ----------------
__global__ void k_pool(const float* __restrict__ pw, const float* __restrict__ pb,
                       const float* __restrict__ pg, const float* __restrict__ pbe,
                       const float* __restrict__ pm, const float* __restrict__ pv) {
    const int HP[4] = {64, 32, 22, 11};
    const int PS[4] = {1, 2, 3, 6};
    const int PLO[4] = {0, 0, 1, 1};
    int b = blockIdx.y;
    int lin = blockIdx.x;
    int j, r;
    if (lin < 1024)      { j = 1; r = lin; }
    else if (lin < 1508) { j = 2; r = lin - 1024; }
    else                 { j = 3; r = lin - 1508; }
    int hp = HP[j], ps = PS[j], plo = PLO[j];
    int oy = r / hp, ox = r % hp;
    __shared__ float avg[256];
    __shared__ float part[256];
    int tt = threadIdx.x;
    int ys = oy * ps - plo, xs = ox * ps - plo;
    int ye = min(ys + ps, 64), xe = min(xs + ps, 64);
    ys = max(ys, 0); xs = max(xs, 0);
    float s = 0.f;
    for (int yy = ys; yy < ye; ++yy)
        for (int xx = xs; xx < xe; ++xx)
            s += g_fused[((size_t)(b * HW) + yy * 64 + xx) * 256 + tt];
    avg[tt] = s * (1.f / (float)((ye - ys) * (xe - xs)));
    __syncthreads();
    int o = tt & 15, ck = tt >> 4;
    const float* wp = pw + j * 256 * 16 + o;
    float a = 0.f;
#pragma unroll
    for (int q = 0; q < 16; ++q) {
        int ci = ck * 16 + q;
        a += avg[ci] * wp[ci * 16];
    }
    part[ck * 16 + o] = a;
    __syncthreads();
    if (tt < 16) {
        float acc = pb[j * 16 + tt];
#pragma unroll
        for (int k2 = 0; k2 < 16; ++k2) acc += part[k2 * 16 + tt];
        int idx = j * 16 + tt;
        float sc = pg[idx] * rsqrtf(pv[idx] + 1e-3f);
        float sh = pbe[idx] - pm[idx] * sc;
        g_pool[((size_t)((j * 2 + b) * HW) + oy * hp + ox) * 16 + tt] = acc * sc + sh;
    }
}

// ---------------- K5: fused ps=1 conv + bilinear upsample + proj + BN ------
__global__ void __launch_bounds__(256) k_proj(
        const float* __restrict__ w, const float* __restrict__ pb,
        const float* __restrict__ g, const float* __restrict__ be,
        const float* __restrict__ m, const float* __restrict__ v,
        const float* __restrict__ pplw, const float* __restrict__ pplb,
        const float* __restrict__ ppg, const float* __restrict__ ppbe,
        const float* __restrict__ ppm, const float* __restrict__ ppv,
        float* __restrict__ out) {
    __shared__ float fv[16][324];
    __shared__ float ws[256 * 16];
    int tid = threadIdx.x;
    int tok0 = blockIdx.x * 16;
    int b2 = tok0 >> 12;
    int pos0 = tok0 & 4095;
    int yy = pos0 >> 6, xx0 = pos0 & 63;
#pragma unroll
    for (int i = 0; i < 4; ++i) {
        int fid = tid + i * 256;
        int px = fid >> 6, c4 = (fid & 63) * 4;
        *(float4*)&fv[px][c4] = *(const float4*)(g_fused + (size_t)(tok0 + px) * 256 + c4);
        *(float4*)&ws[fid * 4] = *(const float4*)(pplw + fid * 4);
    }
    __syncthreads();
    {
        int o = tid & 15, px = tid >> 4;
        float acc = pplb[o];
#pragma unroll 8
        for (int ci = 0; ci < 256; ci += 4) {
            float4 xv = *(const float4*)&fv[px][ci];
            acc += xv.x * ws[ci * 16 + o] + xv.y * ws[(ci + 1) * 16 + o]
                 + xv.z * ws[(ci + 2) * 16 + o] + xv.w * ws[(ci + 3) * 16 + o];
        }
        float sc = ppg[o] * rsqrtf(ppv[o] + 1e-3f);
        float sh = ppbe[o] - ppm[o] * sc;
        fv[px][256 + o] = acc * sc + sh;
    }
    {
        const int HP[3] = {32, 22, 11};
#pragma unroll
        for (int k = 0; k < 3; ++k) {
            int id = tid + k * 256;
            int j = id >> 8;
            int rem = id & 255;
            int c = rem & 15, px = rem >> 4;
            int hp = HP[j];
            float scale = hp * (1.f / 64.f);
            float fy = (yy + 0.5f) * scale - 0.5f;
            float fx = (xx0 + px + 0.5f) * scale - 0.5f;
            float y0f = floorf(fy), x0f = floorf(fx);
            float ty = fy - y0f, tx = fx - x0f;
            int yA = min(max((int)y0f, 0), hp - 1);
            int yB = min(max((int)y0f + 1, 0), hp - 1);
            int xA = min(max((int)x0f, 0), hp - 1);
            int xB = min(max((int)x0f + 1, 0), hp - 1);
            const float* P = g_pool + (size_t)(((j + 1) * 2 + b2) * HW) * 16 + c;
            float v00 = P[(yA * hp + xA) * 16], v01 = P[(yA * hp + xB) * 16];
            float v10 = P[(yB * hp + xA) * 16], v11 = P[(yB * hp + xB) * 16];
            fv[px][272 + j * 16 + c] =
                (1.f - ty) * ((1.f - tx) * v00 + tx * v01)
                + ty * ((1.f - tx) * v10 + tx * v11);
        }
    }
    __syncthreads();
    int co = tid & 63, tg = tid >> 6;
    int r0 = tg * 4;
    float a0 = pb[co], a1 = a0, a2 = a0, a3 = a0;
    const float* wp = w + co;
#pragma unroll 8
    for (int ci = 0; ci < 320; ci += 4) {
        float w0 = wp[ci * 64], w1 = wp[(ci + 1) * 64];
        float w2 = wp[(ci + 2) * 64], w3 = wp[(ci + 3) * 64];
        float4 x0 = *(const float4*)&fv[r0][ci];
        float4 x1 = *(const float4*)&fv[r0 + 1][ci];
        float4 x2 = *(const float4*)&fv[r0 + 2][ci];
        float4 x3 = *(const float4*)&fv[r0 + 3][ci];
        a0 += x0.x * w0 + x0.y * w1 + x0.z * w2 + x0.w * w3;
        a1 += x1.x * w0 + x1.y * w1 + x1.z * w2 + x1.w * w3;
        a2 += x2.x * w0 + x2.y * w1 + x2.z * w2 + x2.w * w3;
        a3 += x3.x * w0 + x3.y * w1 + x3.z * w2 + x3.w * w3;
    }
    float sc = g[co] * rsqrtf(v[co] + 1e-3f);
    float sh = be[co] - m[co] * sc;
    float* op = out + (size_t)(tok0 + r0) * 64 + co;
    op[0]   = fmaxf(a0 * sc + sh, 0.f);
    op[64]  = fmaxf(a1 * sc + sh, 0.f);
    op[128] = fmaxf(a2 * sc + sh, 0.f);
    op[192] = fmaxf(a3 * sc + sh, 0.f);
}

// ---------------- launch ---------------------------------------------------
extern "C" void kernel_launch(void* const* d_in, const int* in_sizes, int n_in,
                              void* d_out, int out_size) {
    const float* x       = (const float*)d_in[0];
    const float* conv_w  = (const float*)d_in[1];
    const float* conv_b  = (const float*)d_in[2];
    const float* bn_g    = (const float*)d_in[3];
    const float* bn_b    = (const float*)d_in[4];
    const float* bn_m    = (const float*)d_in[5];
    const float* bn_v    = (const float*)d_in[6];
    const float* q_w     = (const float*)d_in[7];
    const float* q_b     = (const float*)d_in[8];
    const float* k_w     = (const float*)d_in[9];
    const float* k_b     = (const float*)d_in[10];
    const float* v_w     = (const float*)d_in[11];
    const float* v_b     = (const float*)d_in[12];
    const float* attn_g  = (const float*)d_in[13];
    const float* ppl_w   = (const float*)d_in[14];
    const float* ppl_b   = (const float*)d_in[15];
    const float* ppl_bng = (const float*)d_in[16];
    const float* ppl_bnb = (const float*)d_in[17];
    const float* ppl_bnm = (const float*)d_in[18];
    const float* ppl_bnv = (const float*)d_in[19];
    const float* proj_w  = (const float*)d_in[20];
    const float* proj_b  = (const float*)d_in[21];
    const float* pbn_g   = (const float*)d_in[22];
    const float* pbn_b   = (const float*)d_in[23];
    const float* pbn_m   = (const float*)d_in[24];
    const float* pbn_v   = (const float*)d_in[25];
    float* out = (float*)d_out;

    const int CONV_SMEM = 18576 * 4;  // 74,304 B
    cudaFuncSetAttribute(k_conv, cudaFuncAttributeMaxDynamicSharedMemorySize, CONV_SMEM);

    k_conv<<<dim3(32, 8), 256, CONV_SMEM>>>(x, conv_w, conv_b, bn_g, bn_b, bn_m, bn_v,
                                            q_w, q_b, k_w, k_b, v_w, v_b);
    k_attn<<<dim3(32, 4, 2), 256>>>(attn_g);
    k_pool<<<dim3(1629, 2), 256>>>(ppl_w, ppl_b, ppl_bng, ppl_bnb, ppl_bnm, ppl_bnv);
    k_proj<<<512, 256>>>(proj_w, proj_b, pbn_g, pbn_b, pbn_m, pbn_v,
                         ppl_w, ppl_b, ppl_bng, ppl_bnb, ppl_bnm, ppl_bnv, out);
}